// round 11
// baseline (speedup 1.0000x reference)
#include <cuda_runtime.h>
#include <cstdint>

#define B_    4
#define T_    1024
#define DM    1024
#define NH    16
#define HD    64
#define ROWS  (B_ * T_)        // 4096
#define UNITS (ROWS * NH)      // 65536

// ---------------- static device scratch (no allocations allowed) ----------------
__device__ float g_Y[3][ROWS * DM];       // raw Q/K/V projections   48 MB
__device__ float g_KT[64 * HD * T_];      // sparsified K, [bh][d][t] 16 MB
__device__ float g_V[UNITS * HD];         // sparsified V 16 MB
__device__ float g_Q4v[UNITS * 4];        // top-4 q values
__device__ int   g_Q4i[UNITS * 4];        // top-4 q indices (ascending)
__device__ float g_AO[ROWS * DM];         // attention output 16 MB

// =================== fp32 FFMA SGEMM (QKV): double-buffered smem, 1 sync/chunk ===================
#define BM  128
#define BN  128
#define BKK 16

__device__ __forceinline__ void sgemm_db_body(const float* __restrict__ X,
                                              const float* __restrict__ W,
                                              float* __restrict__ Y) {
    __shared__ float As[2][BKK][BM];
    __shared__ float Bs[2][BKK][BN];
    int tid = threadIdx.x;
    int tx = tid & 15, ty = tid >> 4;
    int m0 = blockIdx.y * BM, n0 = blockIdx.x * BN;

    float acc[8][8];
#pragma unroll
    for (int i = 0; i < 8; ++i)
#pragma unroll
        for (int j = 0; j < 8; ++j) acc[i][j] = 0.f;

    int lr = tid >> 2;   // 0..63
    int lc = tid & 3;    // 0..3

#pragma unroll
    for (int rr = 0; rr < 2; ++rr) {
        int r = lr + rr * 64;
        float4 a = *(const float4*)(X + (size_t)(m0 + r) * DM + lc * 4);
        As[0][lc * 4 + 0][r] = a.x; As[0][lc * 4 + 1][r] = a.y;
        As[0][lc * 4 + 2][r] = a.z; As[0][lc * 4 + 3][r] = a.w;
        float4 b = *(const float4*)(W + (size_t)(n0 + r) * DM + lc * 4);
        Bs[0][lc * 4 + 0][r] = b.x; Bs[0][lc * 4 + 1][r] = b.y;
        Bs[0][lc * 4 + 2][r] = b.z; Bs[0][lc * 4 + 3][r] = b.w;
    }
    __syncthreads();

    for (int c = 0; c < DM / BKK; ++c) {
        int cur = c & 1, nxt = cur ^ 1;
        bool hn = (c + 1) < DM / BKK;
        float4 pa0, pa1, pb0, pb1;
        if (hn) {
            int kn = (c + 1) * BKK;
            pa0 = *(const float4*)(X + (size_t)(m0 + lr) * DM + kn + lc * 4);
            pa1 = *(const float4*)(X + (size_t)(m0 + lr + 64) * DM + kn + lc * 4);
            pb0 = *(const float4*)(W + (size_t)(n0 + lr) * DM + kn + lc * 4);
            pb1 = *(const float4*)(W + (size_t)(n0 + lr + 64) * DM + kn + lc * 4);
        }
#pragma unroll
        for (int kk = 0; kk < BKK; ++kk) {
            float4 a0 = *(const float4*)&As[cur][kk][ty * 8];
            float4 a1 = *(const float4*)&As[cur][kk][ty * 8 + 4];
            float4 b0 = *(const float4*)&Bs[cur][kk][tx * 8];
            float4 b1 = *(const float4*)&Bs[cur][kk][tx * 8 + 4];
            float a[8] = {a0.x, a0.y, a0.z, a0.w, a1.x, a1.y, a1.z, a1.w};
            float b[8] = {b0.x, b0.y, b0.z, b0.w, b1.x, b1.y, b1.z, b1.w};
#pragma unroll
            for (int i = 0; i < 8; ++i)
#pragma unroll
                for (int j = 0; j < 8; ++j) acc[i][j] = fmaf(a[i], b[j], acc[i][j]);
        }
        if (hn) {
            As[nxt][lc * 4 + 0][lr] = pa0.x; As[nxt][lc * 4 + 1][lr] = pa0.y;
            As[nxt][lc * 4 + 2][lr] = pa0.z; As[nxt][lc * 4 + 3][lr] = pa0.w;
            As[nxt][lc * 4 + 0][lr + 64] = pa1.x; As[nxt][lc * 4 + 1][lr + 64] = pa1.y;
            As[nxt][lc * 4 + 2][lr + 64] = pa1.z; As[nxt][lc * 4 + 3][lr + 64] = pa1.w;
            Bs[nxt][lc * 4 + 0][lr] = pb0.x; Bs[nxt][lc * 4 + 1][lr] = pb0.y;
            Bs[nxt][lc * 4 + 2][lr] = pb0.z; Bs[nxt][lc * 4 + 3][lr] = pb0.w;
            Bs[nxt][lc * 4 + 0][lr + 64] = pb1.x; Bs[nxt][lc * 4 + 1][lr + 64] = pb1.y;
            Bs[nxt][lc * 4 + 2][lr + 64] = pb1.z; Bs[nxt][lc * 4 + 3][lr + 64] = pb1.w;
        }
        __syncthreads();
    }
#pragma unroll
    for (int i = 0; i < 8; ++i) {
        float* yp = Y + (size_t)(m0 + ty * 8 + i) * DM + n0 + tx * 8;
        *(float4*)yp = make_float4(acc[i][0], acc[i][1], acc[i][2], acc[i][3]);
        *(float4*)(yp + 4) = make_float4(acc[i][4], acc[i][5], acc[i][6], acc[i][7]);
    }
}

__global__ void __launch_bounds__(256) sgemm_qkv(const float* __restrict__ X,
                                                 const float* __restrict__ Wq,
                                                 const float* __restrict__ Wk,
                                                 const float* __restrict__ Wv) {
    const float* W = (blockIdx.z == 0) ? Wq : (blockIdx.z == 1) ? Wk : Wv;
    sgemm_db_body(X, W, g_Y[blockIdx.z]);
}

// =================== bf16x3 warp-MMA GEMM (O-projection only; no topk downstream) ===================
#define LDW   12

__device__ __forceinline__ unsigned cvt2(float hi, float lo) {
    unsigned r;
    asm("cvt.rn.bf16x2.f32 %0, %1, %2;" : "=r"(r) : "f"(hi), "f"(lo));
    return r;
}
__device__ __forceinline__ void mma_bf16(float* c, const unsigned* a, const unsigned* b) {
    asm volatile(
        "mma.sync.aligned.m16n8k16.row.col.f32.bf16.bf16.f32 "
        "{%0,%1,%2,%3}, {%4,%5,%6,%7}, {%8,%9}, {%0,%1,%2,%3};"
        : "+f"(c[0]), "+f"(c[1]), "+f"(c[2]), "+f"(c[3])
        : "r"(a[0]), "r"(a[1]), "r"(a[2]), "r"(a[3]), "r"(b[0]), "r"(b[1]));
}

__device__ __forceinline__ void split_store3(unsigned* S0, unsigned* S1, unsigned* S2,
                                             int r, int c4, float4 a) {
    unsigned p0 = cvt2(a.y, a.x);
    float h0 = __uint_as_float(p0 & 0xffff0000u), l0 = __uint_as_float(p0 << 16);
    float rx = a.x - l0, ry = a.y - h0;
    unsigned p1 = cvt2(ry, rx);
    float h1 = __uint_as_float(p1 & 0xffff0000u), l1 = __uint_as_float(p1 << 16);
    unsigned p2 = cvt2(ry - h1, rx - l1);
    unsigned q0 = cvt2(a.w, a.z);
    float h2 = __uint_as_float(q0 & 0xffff0000u), l2 = __uint_as_float(q0 << 16);
    float rz = a.z - l2, rw = a.w - h2;
    unsigned q1 = cvt2(rw, rz);
    float h3 = __uint_as_float(q1 & 0xffff0000u), l3 = __uint_as_float(q1 << 16);
    unsigned q2 = cvt2(rw - h3, rz - l3);
    int o = r * LDW + c4 * 2;
    *(uint2*)&S0[o] = make_uint2(p0, q0);
    *(uint2*)&S1[o] = make_uint2(p1, q1);
    *(uint2*)&S2[o] = make_uint2(p2, q2);
}

__global__ void __launch_bounds__(256, 2) mma_gemm_o(const float* __restrict__ Wo,
                                                     float* __restrict__ Y) {
    const float* X = g_AO;
    __shared__ unsigned A0s[128 * LDW], A1s[128 * LDW], A2s[128 * LDW];
    __shared__ unsigned B0s[128 * LDW], B1s[128 * LDW], B2s[128 * LDW];
    int tid = threadIdx.x, lane = tid & 31, wid = tid >> 5;
    int m0 = blockIdx.y * 128, n0 = blockIdx.x * 128;
    int wm = (wid >> 2) * 64, wn = (wid & 3) * 32;
    int gid = lane >> 2, tig = lane & 3;

    float acc[4][4][4];
#pragma unroll
    for (int i = 0; i < 4; ++i)
#pragma unroll
        for (int j = 0; j < 4; ++j)
#pragma unroll
            for (int q = 0; q < 4; ++q) acc[i][j][q] = 0.f;

    int lr = tid >> 2, lc4 = tid & 3;

#pragma unroll
    for (int i = 0; i < 2; ++i) {
        int r = lr + i * 64;
        split_store3(A0s, A1s, A2s, r, lc4, *(const float4*)(X + (size_t)(m0 + r) * DM + lc4 * 4));
        split_store3(B0s, B1s, B2s, r, lc4, *(const float4*)(Wo + (size_t)(n0 + r) * DM + lc4 * 4));
    }
    __syncthreads();

    for (int c = 0; c < DM / 16; ++c) {
        float4 pa[2], pb[2];
        bool has_next = (c + 1) < DM / 16;
        if (has_next) {
            int kn = (c + 1) * 16;
#pragma unroll
            for (int i = 0; i < 2; ++i) {
                int r = lr + i * 64;
                pa[i] = *(const float4*)(X + (size_t)(m0 + r) * DM + kn + lc4 * 4);
                pb[i] = *(const float4*)(Wo + (size_t)(n0 + r) * DM + kn + lc4 * 4);
            }
        }
        {
            unsigned b0[4][2], b1[4][2], b2[4][2];
#pragma unroll
            for (int j = 0; j < 4; ++j) {
                int nn = (wn + j * 8 + gid) * LDW;
                b0[j][0] = B0s[nn + tig]; b0[j][1] = B0s[nn + tig + 4];
                b1[j][0] = B1s[nn + tig]; b1[j][1] = B1s[nn + tig + 4];
                b2[j][0] = B2s[nn + tig]; b2[j][1] = B2s[nn + tig + 4];
            }
            unsigned af[4][4];
            // a0 x {b0, b1, b2}
#pragma unroll
            for (int i = 0; i < 4; ++i) {
                int r0 = (wm + i * 16 + gid) * LDW, r1 = r0 + 8 * LDW;
                af[i][0] = A0s[r0 + tig]; af[i][1] = A0s[r1 + tig];
                af[i][2] = A0s[r0 + tig + 4]; af[i][3] = A0s[r1 + tig + 4];
            }
#pragma unroll
            for (int i = 0; i < 4; ++i)
#pragma unroll
                for (int j = 0; j < 4; ++j) {
                    mma_bf16(acc[i][j], af[i], b0[j]);
                    mma_bf16(acc[i][j], af[i], b1[j]);
                    mma_bf16(acc[i][j], af[i], b2[j]);
                }
            // a1 x {b0, b1}
#pragma unroll
            for (int i = 0; i < 4; ++i) {
                int r0 = (wm + i * 16 + gid) * LDW, r1 = r0 + 8 * LDW;
                af[i][0] = A1s[r0 + tig]; af[i][1] = A1s[r1 + tig];
                af[i][2] = A1s[r0 + tig + 4]; af[i][3] = A1s[r1 + tig + 4];
            }
#pragma unroll
            for (int i = 0; i < 4; ++i)
#pragma unroll
                for (int j = 0; j < 4; ++j) {
                    mma_bf16(acc[i][j], af[i], b0[j]);
                    mma_bf16(acc[i][j], af[i], b1[j]);
                }
            // a2 x b0
#pragma unroll
            for (int i = 0; i < 4; ++i) {
                int r0 = (wm + i * 16 + gid) * LDW, r1 = r0 + 8 * LDW;
                af[i][0] = A2s[r0 + tig]; af[i][1] = A2s[r1 + tig];
                af[i][2] = A2s[r0 + tig + 4]; af[i][3] = A2s[r1 + tig + 4];
            }
#pragma unroll
            for (int i = 0; i < 4; ++i)
#pragma unroll
                for (int j = 0; j < 4; ++j)
                    mma_bf16(acc[i][j], af[i], b0[j]);
        }
        __syncthreads();
        if (has_next) {
#pragma unroll
            for (int i = 0; i < 2; ++i) {
                int r = lr + i * 64;
                split_store3(A0s, A1s, A2s, r, lc4, pa[i]);
                split_store3(B0s, B1s, B2s, r, lc4, pb[i]);
            }
            __syncthreads();
        }
    }

#pragma unroll
    for (int i = 0; i < 4; ++i) {
        int r0 = m0 + wm + i * 16 + gid, r1 = r0 + 8;
#pragma unroll
        for (int j = 0; j < 4; ++j) {
            int cb = n0 + wn + j * 8 + 2 * tig;
            *(float2*)(Y + (size_t)r0 * DM + cb) = make_float2(acc[i][j][0], acc[i][j][1]);
            *(float2*)(Y + (size_t)r1 * DM + cb) = make_float2(acc[i][j][2], acc[i][j][3]);
        }
    }
}

// ---------------- sparsify: per (b,h,t) keep top-4 by |v| (tie -> lower index) ----------------
__global__ void __launch_bounds__(256) sparsify_kernel() {
    int warp = (blockIdx.x * blockDim.x + threadIdx.x) >> 5;
    int lane = threadIdx.x & 31;
    int tensor = warp / UNITS;            // 0=q 1=k 2=v
    int idx = warp - tensor * UNITS;
    int row = idx >> 4;                   // b*T + t
    int h = idx & 15;

    const float* Y = g_Y[tensor];
    float v0 = Y[(size_t)row * DM + h * HD + lane];
    float v1 = Y[(size_t)row * DM + h * HD + 32 + lane];
    unsigned a0 = __float_as_uint(v0) & 0x7fffffffu;
    unsigned a1 = __float_as_uint(v1) & 0x7fffffffu;
    unsigned long long k0 = ((unsigned long long)a0 << 32) | (unsigned)(63 - lane);
    unsigned long long k1 = ((unsigned long long)a1 << 32) | (unsigned)(31 - lane);

    bool s0 = false, s1 = false;
    int selD[4]; float selV[4];
#pragma unroll
    for (int r = 0; r < 4; ++r) {
        unsigned long long m = (k0 > k1) ? k0 : k1;
#pragma unroll
        for (int o = 16; o; o >>= 1) {
            unsigned long long t2 = __shfl_xor_sync(0xffffffffu, m, o);
            if (t2 > m) m = t2;
        }
        int d = 63 - (int)(unsigned)(m & 0xffffffffULL);
        selD[r] = d;
        float srcv = (d < 32) ? v0 : v1;
        selV[r] = __shfl_sync(0xffffffffu, srcv, d & 31);
        if (d < 32) { if (lane == d) { k0 = 0; s0 = true; } }
        else        { if (lane == (d - 32)) { k1 = 0; s1 = true; } }
    }

    int b = row >> 10, t = row & (T_ - 1);
    int bh = b * NH + h;

    if (tensor == 0) {
        if (lane == 0) {
#pragma unroll
            for (int a = 0; a < 3; ++a)
#pragma unroll
                for (int c = 0; c < 3; ++c)
                    if (selD[c + 1] < selD[c]) {
                        int td = selD[c]; selD[c] = selD[c + 1]; selD[c + 1] = td;
                        float tv = selV[c]; selV[c] = selV[c + 1]; selV[c + 1] = tv;
                    }
            size_t base = ((size_t)bh * T_ + t) * 4;
#pragma unroll
            for (int r = 0; r < 4; ++r) { g_Q4i[base + r] = selD[r]; g_Q4v[base + r] = selV[r]; }
        }
    } else if (tensor == 1) {
        g_KT[((size_t)bh * HD + lane) * T_ + t]      = s0 ? v0 : 0.f;
        g_KT[((size_t)bh * HD + 32 + lane) * T_ + t] = s1 ? v1 : 0.f;
    } else {
        g_V[((size_t)bh * T_ + t) * HD + lane]      = s0 ? v0 : 0.f;
        g_V[((size_t)bh * T_ + t) * HD + 32 + lane] = s1 ? v1 : 0.f;
    }
}

// ---------------- attention: warp-bisection top-64 selection ----------------
// jax top_k ranks positives > zeros > negatives, tie -> lower index.
//   n<=64          : take all (thr=0, need_eq=0)
//   P<64<=P+Z      : thr = key(0.0), need_eq = 64-P        (no selection work)
//   otherwise      : compact candidate KEYS (positives if P>=64 else all valid),
//                    warp-0 radix bisection finds 64th-largest key (thr) and
//                    need_eq = 64 - count(key > thr). Tie semantics identical.
__global__ void __launch_bounds__(256) attn_kernel() {
    int t  = blockIdx.x;
    int bh = blockIdx.y;
    int tid = threadIdx.x;
    int lane = tid & 31, wid = tid >> 5;

    __shared__ float    sc[T_];
    __shared__ unsigned su[T_];
    __shared__ unsigned candK[T_];
    __shared__ int      s_C, s_cnt, s_need;
    __shared__ unsigned s_thr;
    __shared__ float    s_red[2];
    __shared__ int      selid[64];
    __shared__ float    selsc[64], selw[64];
    __shared__ int      wsum[8];
    __shared__ int      cls_sum[8];
    __shared__ float    part[256];
    __shared__ int      qidx[4];
    __shared__ float    qval[4];

    if (tid == 0) s_cnt = 0;
    if (tid < 4) {
        size_t qb = ((size_t)bh * T_ + t) * 4 + tid;
        qidx[tid] = g_Q4i[qb];
        qval[tid] = g_Q4v[qb];
    }
    __syncthreads();

    const float NEG = __int_as_float(0xff800000);
    const float* K0 = g_KT + ((size_t)bh * HD + qidx[0]) * T_;
    const float* K1 = g_KT + ((size_t)bh * HD + qidx[1]) * T_;
    const float* K2 = g_KT + ((size_t)bh * HD + qidx[2]) * T_;
    const float* K3 = g_KT + ((size_t)bh * HD + qidx[3]) * T_;
    float q0 = qval[0], q1 = qval[1], q2 = qval[2], q3 = qval[3];

    int n = t + 1;
#pragma unroll
    for (int r = 0; r < 4; ++r) {
        int i = tid + r * 256;
        unsigned u = 0u;
        if (i < n) {
            float s = (q0 * K0[i] + q1 * K1[i] + q2 * K2[i] + q3 * K3[i]) * 0.125f;
            sc[i] = s;
            unsigned bits = __float_as_uint(s);
            if (bits == 0x80000000u) bits = 0u;                   // canonicalize -0
            u = (bits & 0x80000000u) ? ~bits : (bits | 0x80000000u);
        }
        su[i] = u;                                                // pads: key 0 (never selected)
    }
    __syncthreads();

    int base = tid * 4;
    unsigned u4[4];
    int pl = 0, zl = 0;
#pragma unroll
    for (int c = 0; c < 4; ++c) {
        u4[c] = su[base + c];
        pl += (u4[c] > 0x80000000u);
        zl += (u4[c] == 0x80000000u);
    }
    int packedc = pl | (zl << 16);
#pragma unroll
    for (int o = 16; o; o >>= 1) packedc += __shfl_xor_sync(0xffffffffu, packedc, o);
    if (lane == 0) cls_sum[wid] = packedc;
    __syncthreads();
    int tot = 0;
#pragma unroll
    for (int w = 0; w < 8; ++w) tot += cls_sum[w];
    int P = tot & 0xffff, Z = tot >> 16;

    unsigned thr = 0u; int need_eq = 0;
    if (n <= 64) {
        thr = 0u; need_eq = 0;
    } else if (P < 64 && P + Z >= 64) {
        thr = 0x80000000u; need_eq = 64 - P;
    } else {
        // compact candidate keys: positives if P>=64, else all valid (n > 64 here)
        bool wantPos = (P >= 64);
        if (tid == 0) s_C = 0;
        __syncthreads();
#pragma unroll
        for (int c = 0; c < 4; ++c) {
            int i = base + c;
            bool take = wantPos ? (u4[c] > 0x80000000u) : (i < n);
            unsigned m = __ballot_sync(0xffffffffu, take);
            int cw = __popc(m);
            int pos = __popc(m & ((1u << lane) - 1u));
            int wb = 0;
            if (lane == 0 && cw) wb = atomicAdd(&s_C, cw);
            wb = __shfl_sync(0xffffffffu, wb, 0);
            if (take) candK[wb + pos] = u4[c];
        }
        __syncthreads();
        int C = s_C;
        // warp 0: radix bisection for 64th-largest key among candK[0..C)
        if (wid == 0) {
            unsigned kr[8];
            bool fits = (C <= 256);
#pragma unroll
            for (int q = 0; q < 8; ++q) {
                int j = lane + q * 32;
                kr[q] = (fits && j < C) ? candK[j] : 0u;   // pad 0: never >= any test value
            }
            unsigned v = 0u;
            for (int bit = 31; bit >= 0; --bit) {
                unsigned test = v | (1u << bit);
                int cnt = 0;
                if (fits) {
#pragma unroll
                    for (int q = 0; q < 8; ++q) cnt += (kr[q] >= test);
                } else {
                    for (int j = lane; j < C; j += 32) cnt += (candK[j] >= test);
                }
                cnt = (int)__reduce_add_sync(0xffffffffu, (unsigned)cnt);
                if (cnt >= 64) v = test;
            }
            int cgt = 0;
            if (fits) {
#pragma unroll
                for (int q = 0; q < 8; ++q) cgt += (kr[q] > v);
            } else {
                for (int j = lane; j < C; j += 32) cgt += (candK[j] > v);
            }
            cgt = (int)__reduce_add_sync(0xffffffffu, (unsigned)cgt);
            if (lane == 0) { s_thr = v; s_need = 64 - cgt; }
        }
        __syncthreads();
        thr = s_thr; need_eq = s_need;
    }

    // ---- final selection: u > thr, plus first need_eq equals in index order ----
    int eqf[4]; int local = 0;
#pragma unroll
    for (int c = 0; c < 4; ++c) { eqf[c] = (u4[c] == thr) ? 1 : 0; local += eqf[c]; }
    int v = local;
#pragma unroll
    for (int o = 1; o < 32; o <<= 1) {
        int x = __shfl_up_sync(0xffffffffu, v, o);
        if (lane >= o) v += x;
    }
    if (lane == 31) wsum[wid] = v;
    __syncthreads();
    if (tid == 0) { int a = 0; for (int w = 0; w < 8; ++w) { int x = wsum[w]; wsum[w] = a; a += x; } }
    __syncthreads();
    int run = v - local + wsum[wid];

#pragma unroll
    for (int c = 0; c < 4; ++c) {
        int i = base + c; unsigned u = u4[c];
        bool sel = false;
        if (u > thr) sel = true;
        else if (eqf[c]) { sel = (run < need_eq); run++; }
        if (sel) {
            int p = atomicAdd(&s_cnt, 1);
            if (p < 64) { selid[p] = i; selsc[p] = sc[i]; }
        }
    }
    __syncthreads();
    int cnt = s_cnt; if (cnt > 64) cnt = 64;

    if (tid < 64) {
        float xx = (tid < cnt) ? selsc[tid] : NEG;
#pragma unroll
        for (int o = 16; o; o >>= 1) xx = fmaxf(xx, __shfl_xor_sync(0xffffffffu, xx, o));
        if ((tid & 31) == 0) s_red[tid >> 5] = xx;
    }
    __syncthreads();
    float m = fmaxf(s_red[0], s_red[1]);
    __syncthreads();
    if (tid < 64) {
        float e = (tid < cnt) ? __expf(selsc[tid] - m) : 0.f;
        selw[tid] = e;
#pragma unroll
        for (int o = 16; o; o >>= 1) e += __shfl_xor_sync(0xffffffffu, e, o);
        if ((tid & 31) == 0) s_red[tid >> 5] = e;
    }
    __syncthreads();
    float invZ = 1.f / (s_red[0] + s_red[1]);

    int g = tid >> 6, d = tid & 63;
    float acc = 0.f;
    const float* Vb = g_V + (size_t)bh * T_ * HD;
    for (int p = g; p < cnt; p += 4) acc += selw[p] * Vb[(size_t)selid[p] * HD + d];
    part[tid] = acc;
    __syncthreads();
    if (tid < 64) {
        float o = (part[tid] + part[tid + 64] + part[tid + 128] + part[tid + 192]) * invZ;
        int b = bh >> 4, h = bh & 15;
        g_AO[((size_t)(b * T_ + t)) * DM + h * HD + tid] = o;
    }
}

// ---------------- launch ----------------
extern "C" void kernel_launch(void* const* d_in, const int* in_sizes, int n_in,
                              void* d_out, int out_size) {
    const float* x  = (const float*)d_in[0];
    const float* wq = (const float*)d_in[1];
    const float* wk = (const float*)d_in[2];
    const float* wv = (const float*)d_in[3];
    const float* wo = (const float*)d_in[4];
    float* out = (float*)d_out;

    sgemm_qkv<<<dim3(DM / BN, ROWS / BM, 3), 256>>>(x, wq, wk, wv);

    sparsify_kernel<<<(3 * UNITS) / 8, 256>>>();

    attn_kernel<<<dim3(T_, B_ * NH), 256>>>();

    mma_gemm_o<<<dim3(DM / 128, ROWS / 128, 1), 256>>>(wo, out);
}

// round 12
// speedup vs baseline: 1.0052x; 1.0052x over previous
#include <cuda_runtime.h>
#include <cstdint>

#define B_    4
#define T_    1024
#define DM    1024
#define NH    16
#define HD    64
#define ROWS  (B_ * T_)        // 4096
#define UNITS (ROWS * NH)      // 65536

// ---------------- static device scratch (no allocations allowed) ----------------
__device__ float g_Y[3][ROWS * DM];       // raw Q/K/V projections   48 MB
__device__ float g_KT[64 * HD * T_];      // sparsified K, [bh][d][t] 16 MB
__device__ float g_V[UNITS * HD];         // sparsified V 16 MB
__device__ float g_Q4v[UNITS * 4];        // top-4 q values
__device__ int   g_Q4i[UNITS * 4];        // top-4 q indices (ascending)
__device__ float g_AO[ROWS * DM];         // attention output 16 MB

// =================== fp32 FFMA SGEMM (QKV): double-buffered smem, 1 sync/chunk ===================
#define BM  128
#define BN  128
#define BKK 16

__device__ __forceinline__ void sgemm_db_body(const float* __restrict__ X,
                                              const float* __restrict__ W,
                                              float* __restrict__ Y) {
    __shared__ float As[2][BKK][BM];
    __shared__ float Bs[2][BKK][BN];
    int tid = threadIdx.x;
    int tx = tid & 15, ty = tid >> 4;
    int m0 = blockIdx.y * BM, n0 = blockIdx.x * BN;

    float acc[8][8];
#pragma unroll
    for (int i = 0; i < 8; ++i)
#pragma unroll
        for (int j = 0; j < 8; ++j) acc[i][j] = 0.f;

    int lr = tid >> 2;   // 0..63
    int lc = tid & 3;    // 0..3

#pragma unroll
    for (int rr = 0; rr < 2; ++rr) {
        int r = lr + rr * 64;
        float4 a = *(const float4*)(X + (size_t)(m0 + r) * DM + lc * 4);
        As[0][lc * 4 + 0][r] = a.x; As[0][lc * 4 + 1][r] = a.y;
        As[0][lc * 4 + 2][r] = a.z; As[0][lc * 4 + 3][r] = a.w;
        float4 b = *(const float4*)(W + (size_t)(n0 + r) * DM + lc * 4);
        Bs[0][lc * 4 + 0][r] = b.x; Bs[0][lc * 4 + 1][r] = b.y;
        Bs[0][lc * 4 + 2][r] = b.z; Bs[0][lc * 4 + 3][r] = b.w;
    }
    __syncthreads();

    for (int c = 0; c < DM / BKK; ++c) {
        int cur = c & 1, nxt = cur ^ 1;
        bool hn = (c + 1) < DM / BKK;
        float4 pa0, pa1, pb0, pb1;
        if (hn) {
            int kn = (c + 1) * BKK;
            pa0 = *(const float4*)(X + (size_t)(m0 + lr) * DM + kn + lc * 4);
            pa1 = *(const float4*)(X + (size_t)(m0 + lr + 64) * DM + kn + lc * 4);
            pb0 = *(const float4*)(W + (size_t)(n0 + lr) * DM + kn + lc * 4);
            pb1 = *(const float4*)(W + (size_t)(n0 + lr + 64) * DM + kn + lc * 4);
        }
#pragma unroll
        for (int kk = 0; kk < BKK; ++kk) {
            float4 a0 = *(const float4*)&As[cur][kk][ty * 8];
            float4 a1 = *(const float4*)&As[cur][kk][ty * 8 + 4];
            float4 b0 = *(const float4*)&Bs[cur][kk][tx * 8];
            float4 b1 = *(const float4*)&Bs[cur][kk][tx * 8 + 4];
            float a[8] = {a0.x, a0.y, a0.z, a0.w, a1.x, a1.y, a1.z, a1.w};
            float b[8] = {b0.x, b0.y, b0.z, b0.w, b1.x, b1.y, b1.z, b1.w};
#pragma unroll
            for (int i = 0; i < 8; ++i)
#pragma unroll
                for (int j = 0; j < 8; ++j) acc[i][j] = fmaf(a[i], b[j], acc[i][j]);
        }
        if (hn) {
            As[nxt][lc * 4 + 0][lr] = pa0.x; As[nxt][lc * 4 + 1][lr] = pa0.y;
            As[nxt][lc * 4 + 2][lr] = pa0.z; As[nxt][lc * 4 + 3][lr] = pa0.w;
            As[nxt][lc * 4 + 0][lr + 64] = pa1.x; As[nxt][lc * 4 + 1][lr + 64] = pa1.y;
            As[nxt][lc * 4 + 2][lr + 64] = pa1.z; As[nxt][lc * 4 + 3][lr + 64] = pa1.w;
            Bs[nxt][lc * 4 + 0][lr] = pb0.x; Bs[nxt][lc * 4 + 1][lr] = pb0.y;
            Bs[nxt][lc * 4 + 2][lr] = pb0.z; Bs[nxt][lc * 4 + 3][lr] = pb0.w;
            Bs[nxt][lc * 4 + 0][lr + 64] = pb1.x; Bs[nxt][lc * 4 + 1][lr + 64] = pb1.y;
            Bs[nxt][lc * 4 + 2][lr + 64] = pb1.z; Bs[nxt][lc * 4 + 3][lr + 64] = pb1.w;
        }
        __syncthreads();
    }
#pragma unroll
    for (int i = 0; i < 8; ++i) {
        float* yp = Y + (size_t)(m0 + ty * 8 + i) * DM + n0 + tx * 8;
        *(float4*)yp = make_float4(acc[i][0], acc[i][1], acc[i][2], acc[i][3]);
        *(float4*)(yp + 4) = make_float4(acc[i][4], acc[i][5], acc[i][6], acc[i][7]);
    }
}

__global__ void __launch_bounds__(256) sgemm_qkv(const float* __restrict__ X,
                                                 const float* __restrict__ Wq,
                                                 const float* __restrict__ Wk,
                                                 const float* __restrict__ Wv) {
    const float* W = (blockIdx.z == 0) ? Wq : (blockIdx.z == 1) ? Wk : Wv;
    sgemm_db_body(X, W, g_Y[blockIdx.z]);
}

// =================== bf16x3 warp-MMA GEMM (O-projection only; no topk downstream) ===================
#define LDW   12

__device__ __forceinline__ unsigned cvt2(float hi, float lo) {
    unsigned r;
    asm("cvt.rn.bf16x2.f32 %0, %1, %2;" : "=r"(r) : "f"(hi), "f"(lo));
    return r;
}
__device__ __forceinline__ void mma_bf16(float* c, const unsigned* a, const unsigned* b) {
    asm volatile(
        "mma.sync.aligned.m16n8k16.row.col.f32.bf16.bf16.f32 "
        "{%0,%1,%2,%3}, {%4,%5,%6,%7}, {%8,%9}, {%0,%1,%2,%3};"
        : "+f"(c[0]), "+f"(c[1]), "+f"(c[2]), "+f"(c[3])
        : "r"(a[0]), "r"(a[1]), "r"(a[2]), "r"(a[3]), "r"(b[0]), "r"(b[1]));
}

__device__ __forceinline__ void split_store3(unsigned* S0, unsigned* S1, unsigned* S2,
                                             int r, int c4, float4 a) {
    unsigned p0 = cvt2(a.y, a.x);
    float h0 = __uint_as_float(p0 & 0xffff0000u), l0 = __uint_as_float(p0 << 16);
    float rx = a.x - l0, ry = a.y - h0;
    unsigned p1 = cvt2(ry, rx);
    float h1 = __uint_as_float(p1 & 0xffff0000u), l1 = __uint_as_float(p1 << 16);
    unsigned p2 = cvt2(ry - h1, rx - l1);
    unsigned q0 = cvt2(a.w, a.z);
    float h2 = __uint_as_float(q0 & 0xffff0000u), l2 = __uint_as_float(q0 << 16);
    float rz = a.z - l2, rw = a.w - h2;
    unsigned q1 = cvt2(rw, rz);
    float h3 = __uint_as_float(q1 & 0xffff0000u), l3 = __uint_as_float(q1 << 16);
    unsigned q2 = cvt2(rw - h3, rz - l3);
    int o = r * LDW + c4 * 2;
    *(uint2*)&S0[o] = make_uint2(p0, q0);
    *(uint2*)&S1[o] = make_uint2(p1, q1);
    *(uint2*)&S2[o] = make_uint2(p2, q2);
}

__global__ void __launch_bounds__(256, 2) mma_gemm_o(const float* __restrict__ Wo,
                                                     float* __restrict__ Y) {
    const float* X = g_AO;
    __shared__ unsigned A0s[128 * LDW], A1s[128 * LDW], A2s[128 * LDW];
    __shared__ unsigned B0s[128 * LDW], B1s[128 * LDW], B2s[128 * LDW];
    int tid = threadIdx.x, lane = tid & 31, wid = tid >> 5;
    int m0 = blockIdx.y * 128, n0 = blockIdx.x * 128;
    int wm = (wid >> 2) * 64, wn = (wid & 3) * 32;
    int gid = lane >> 2, tig = lane & 3;

    float acc[4][4][4];
#pragma unroll
    for (int i = 0; i < 4; ++i)
#pragma unroll
        for (int j = 0; j < 4; ++j)
#pragma unroll
            for (int q = 0; q < 4; ++q) acc[i][j][q] = 0.f;

    int lr = tid >> 2, lc4 = tid & 3;

#pragma unroll
    for (int i = 0; i < 2; ++i) {
        int r = lr + i * 64;
        split_store3(A0s, A1s, A2s, r, lc4, *(const float4*)(X + (size_t)(m0 + r) * DM + lc4 * 4));
        split_store3(B0s, B1s, B2s, r, lc4, *(const float4*)(Wo + (size_t)(n0 + r) * DM + lc4 * 4));
    }
    __syncthreads();

    for (int c = 0; c < DM / 16; ++c) {
        float4 pa[2], pb[2];
        bool has_next = (c + 1) < DM / 16;
        if (has_next) {
            int kn = (c + 1) * 16;
#pragma unroll
            for (int i = 0; i < 2; ++i) {
                int r = lr + i * 64;
                pa[i] = *(const float4*)(X + (size_t)(m0 + r) * DM + kn + lc4 * 4);
                pb[i] = *(const float4*)(Wo + (size_t)(n0 + r) * DM + kn + lc4 * 4);
            }
        }
        {
            unsigned b0[4][2], b1[4][2], b2[4][2];
#pragma unroll
            for (int j = 0; j < 4; ++j) {
                int nn = (wn + j * 8 + gid) * LDW;
                b0[j][0] = B0s[nn + tig]; b0[j][1] = B0s[nn + tig + 4];
                b1[j][0] = B1s[nn + tig]; b1[j][1] = B1s[nn + tig + 4];
                b2[j][0] = B2s[nn + tig]; b2[j][1] = B2s[nn + tig + 4];
            }
            unsigned af[4][4];
#pragma unroll
            for (int i = 0; i < 4; ++i) {
                int r0 = (wm + i * 16 + gid) * LDW, r1 = r0 + 8 * LDW;
                af[i][0] = A0s[r0 + tig]; af[i][1] = A0s[r1 + tig];
                af[i][2] = A0s[r0 + tig + 4]; af[i][3] = A0s[r1 + tig + 4];
            }
#pragma unroll
            for (int i = 0; i < 4; ++i)
#pragma unroll
                for (int j = 0; j < 4; ++j) {
                    mma_bf16(acc[i][j], af[i], b0[j]);
                    mma_bf16(acc[i][j], af[i], b1[j]);
                    mma_bf16(acc[i][j], af[i], b2[j]);
                }
#pragma unroll
            for (int i = 0; i < 4; ++i) {
                int r0 = (wm + i * 16 + gid) * LDW, r1 = r0 + 8 * LDW;
                af[i][0] = A1s[r0 + tig]; af[i][1] = A1s[r1 + tig];
                af[i][2] = A1s[r0 + tig + 4]; af[i][3] = A1s[r1 + tig + 4];
            }
#pragma unroll
            for (int i = 0; i < 4; ++i)
#pragma unroll
                for (int j = 0; j < 4; ++j) {
                    mma_bf16(acc[i][j], af[i], b0[j]);
                    mma_bf16(acc[i][j], af[i], b1[j]);
                }
#pragma unroll
            for (int i = 0; i < 4; ++i) {
                int r0 = (wm + i * 16 + gid) * LDW, r1 = r0 + 8 * LDW;
                af[i][0] = A2s[r0 + tig]; af[i][1] = A2s[r1 + tig];
                af[i][2] = A2s[r0 + tig + 4]; af[i][3] = A2s[r1 + tig + 4];
            }
#pragma unroll
            for (int i = 0; i < 4; ++i)
#pragma unroll
                for (int j = 0; j < 4; ++j)
                    mma_bf16(acc[i][j], af[i], b0[j]);
        }
        __syncthreads();
        if (has_next) {
#pragma unroll
            for (int i = 0; i < 2; ++i) {
                int r = lr + i * 64;
                split_store3(A0s, A1s, A2s, r, lc4, pa[i]);
                split_store3(B0s, B1s, B2s, r, lc4, pb[i]);
            }
            __syncthreads();
        }
    }

#pragma unroll
    for (int i = 0; i < 4; ++i) {
        int r0 = m0 + wm + i * 16 + gid, r1 = r0 + 8;
#pragma unroll
        for (int j = 0; j < 4; ++j) {
            int cb = n0 + wn + j * 8 + 2 * tig;
            *(float2*)(Y + (size_t)r0 * DM + cb) = make_float2(acc[i][j][0], acc[i][j][1]);
            *(float2*)(Y + (size_t)r1 * DM + cb) = make_float2(acc[i][j][2], acc[i][j][3]);
        }
    }
}

// ---------------- sparsify: per (b,h,t) keep top-4 by |v| (tie -> lower index) ----------------
__global__ void __launch_bounds__(256) sparsify_kernel() {
    int warp = (blockIdx.x * blockDim.x + threadIdx.x) >> 5;
    int lane = threadIdx.x & 31;
    int tensor = warp / UNITS;            // 0=q 1=k 2=v
    int idx = warp - tensor * UNITS;
    int row = idx >> 4;                   // b*T + t
    int h = idx & 15;

    const float* Y = g_Y[tensor];
    float v0 = Y[(size_t)row * DM + h * HD + lane];
    float v1 = Y[(size_t)row * DM + h * HD + 32 + lane];
    unsigned a0 = __float_as_uint(v0) & 0x7fffffffu;
    unsigned a1 = __float_as_uint(v1) & 0x7fffffffu;
    unsigned long long k0 = ((unsigned long long)a0 << 32) | (unsigned)(63 - lane);
    unsigned long long k1 = ((unsigned long long)a1 << 32) | (unsigned)(31 - lane);

    bool s0 = false, s1 = false;
    int selD[4]; float selV[4];
#pragma unroll
    for (int r = 0; r < 4; ++r) {
        unsigned long long m = (k0 > k1) ? k0 : k1;
#pragma unroll
        for (int o = 16; o; o >>= 1) {
            unsigned long long t2 = __shfl_xor_sync(0xffffffffu, m, o);
            if (t2 > m) m = t2;
        }
        int d = 63 - (int)(unsigned)(m & 0xffffffffULL);
        selD[r] = d;
        float srcv = (d < 32) ? v0 : v1;
        selV[r] = __shfl_sync(0xffffffffu, srcv, d & 31);
        if (d < 32) { if (lane == d) { k0 = 0; s0 = true; } }
        else        { if (lane == (d - 32)) { k1 = 0; s1 = true; } }
    }

    int b = row >> 10, t = row & (T_ - 1);
    int bh = b * NH + h;

    if (tensor == 0) {
        if (lane == 0) {
#pragma unroll
            for (int a = 0; a < 3; ++a)
#pragma unroll
                for (int c = 0; c < 3; ++c)
                    if (selD[c + 1] < selD[c]) {
                        int td = selD[c]; selD[c] = selD[c + 1]; selD[c + 1] = td;
                        float tv = selV[c]; selV[c] = selV[c + 1]; selV[c + 1] = tv;
                    }
            size_t base = ((size_t)bh * T_ + t) * 4;
#pragma unroll
            for (int r = 0; r < 4; ++r) { g_Q4i[base + r] = selD[r]; g_Q4v[base + r] = selV[r]; }
        }
    } else if (tensor == 1) {
        g_KT[((size_t)bh * HD + lane) * T_ + t]      = s0 ? v0 : 0.f;
        g_KT[((size_t)bh * HD + 32 + lane) * T_ + t] = s1 ? v1 : 0.f;
    } else {
        g_V[((size_t)bh * T_ + t) * HD + lane]      = s0 ? v0 : 0.f;
        g_V[((size_t)bh * T_ + t) * HD + 32 + lane] = s1 ? v1 : 0.f;
    }
}

// ---------------- attention: proven block-radix top-64 (round-9 version) ----------------
__global__ void __launch_bounds__(256) attn_kernel() {
    int t  = blockIdx.x;
    int bh = blockIdx.y;
    int tid = threadIdx.x;
    int lane = tid & 31, wid = tid >> 5;

    __shared__ float    sc[T_];
    __shared__ unsigned su[T_];
    __shared__ int      hist[256];
    __shared__ int      candA[T_], candB[T_];
    __shared__ int      s_bin, s_remsh, s_C, s_cnt;
    __shared__ float    s_red[2];
    __shared__ int      selid[64];
    __shared__ float    selsc[64], selw[64];
    __shared__ int      wsum[8];
    __shared__ int      cls_sum[8];
    __shared__ float    part[256];
    __shared__ int      qidx[4];
    __shared__ float    qval[4];

    if (tid == 0) s_cnt = 0;
    if (tid < 4) {
        size_t qb = ((size_t)bh * T_ + t) * 4 + tid;
        qidx[tid] = g_Q4i[qb];
        qval[tid] = g_Q4v[qb];
    }
    __syncthreads();

    const float NEG = __int_as_float(0xff800000);
    const float* K0 = g_KT + ((size_t)bh * HD + qidx[0]) * T_;
    const float* K1 = g_KT + ((size_t)bh * HD + qidx[1]) * T_;
    const float* K2 = g_KT + ((size_t)bh * HD + qidx[2]) * T_;
    const float* K3 = g_KT + ((size_t)bh * HD + qidx[3]) * T_;
    float q0 = qval[0], q1 = qval[1], q2 = qval[2], q3 = qval[3];

    int n = t + 1;
#pragma unroll
    for (int r = 0; r < 4; ++r) {
        int i = tid + r * 256;
        unsigned u = 0u;
        if (i < n) {
            float s = (q0 * K0[i] + q1 * K1[i] + q2 * K2[i] + q3 * K3[i]) * 0.125f;
            sc[i] = s;
            unsigned bits = __float_as_uint(s);
            if (bits == 0x80000000u) bits = 0u;
            u = (bits & 0x80000000u) ? ~bits : (bits | 0x80000000u);
        }
        su[i] = u;
    }
    __syncthreads();

    int base = tid * 4;
    unsigned u4[4];
    int pl = 0, zl = 0;
#pragma unroll
    for (int c = 0; c < 4; ++c) {
        u4[c] = su[base + c];
        pl += (u4[c] > 0x80000000u);
        zl += (u4[c] == 0x80000000u);
    }
    int packedc = pl | (zl << 16);
#pragma unroll
    for (int o = 16; o; o >>= 1) packedc += __shfl_xor_sync(0xffffffffu, packedc, o);
    if (lane == 0) cls_sum[wid] = packedc;
    __syncthreads();
    int tot = 0;
#pragma unroll
    for (int w = 0; w < 8; ++w) tot += cls_sum[w];
    int P = tot & 0xffff, Z = tot >> 16;

    unsigned thr = 0u; int need_eq = 0;
    if (n <= 64) {
        thr = 0u; need_eq = 0;
    } else if (P < 64 && P + Z >= 64) {
        thr = 0x80000000u; need_eq = 64 - P;
    } else {
        bool wantPos = (P >= 64);
        if (tid == 0) s_C = 0;
        __syncthreads();
#pragma unroll
        for (int c = 0; c < 4; ++c) {
            int i = base + c;
            bool take = wantPos ? (u4[c] > 0x80000000u) : (i < n);
            unsigned m = __ballot_sync(0xffffffffu, take);
            int cw = __popc(m);
            int pos = __popc(m & ((1u << lane) - 1u));
            int wb = 0;
            if (lane == 0 && cw) wb = atomicAdd(&s_C, cw);
            wb = __shfl_sync(0xffffffffu, wb, 0);
            if (take) candA[wb + pos] = i;
        }
        __syncthreads();
        int C = s_C;
        __syncthreads();
        int rem = 64;
        unsigned pref = 0u;
        int* cur = candA; int* nxt = candB;
        bool fullkey = true;
        for (int shift = 24; shift >= 0; shift -= 8) {
            if (C == 1) { fullkey = false; break; }
            hist[tid] = 0;
            if (tid == 0) s_C = 0;
            __syncthreads();
            int rounds = (C + 255) >> 8;
            for (int r = 0; r < rounds; ++r) {
                int j = r * 256 + tid;
                int b = (j < C) ? (int)((su[cur[j]] >> shift) & 255u) : -1;
                unsigned m = __match_any_sync(0xffffffffu, b);
                if (b >= 0 && (int)__ffs(m) - 1 == lane) atomicAdd(&hist[b], __popc(m));
            }
            __syncthreads();
            if (wid == 0) {
                int bs = lane * 8;
                int loc[8]; int ssum = 0;
#pragma unroll
                for (int k = 7; k >= 0; --k) { ssum += hist[bs + k]; loc[k] = ssum; }
                int g = ssum;
#pragma unroll
                for (int off = 1; off < 32; off <<= 1) {
                    int v = __shfl_down_sync(0xffffffffu, g, off);
                    if (lane + off < 32) g += v;
                }
                int Hh = g - ssum;
#pragma unroll
                for (int k = 7; k >= 0; --k) {
                    int suf = loc[k] + Hh;
                    int nx2 = (k == 7) ? Hh : (loc[k + 1] + Hh);
                    if (suf >= rem && nx2 < rem) { s_bin = bs + k; s_remsh = rem - nx2; }
                }
            }
            __syncthreads();
            int b2 = s_bin; rem = s_remsh;
            int rounds2 = (C + 255) >> 8;
            for (int r = 0; r < rounds2; ++r) {
                int j = r * 256 + tid;
                if (j < C && (int)((su[cur[j]] >> shift) & 255u) == b2) {
                    int p = atomicAdd(&s_C, 1); nxt[p] = cur[j];
                }
            }
            __syncthreads();
            C = s_C;
            __syncthreads();
            pref |= (unsigned)b2 << shift;
            int* tsw = cur; cur = nxt; nxt = tsw;
        }
        thr = fullkey ? pref : su[cur[0]];
        need_eq = rem;
    }

    int eqf[4]; int local = 0;
#pragma unroll
    for (int c = 0; c < 4; ++c) { eqf[c] = (u4[c] == thr) ? 1 : 0; local += eqf[c]; }
    int v = local;
#pragma unroll
    for (int o = 1; o < 32; o <<= 1) {
        int x = __shfl_up_sync(0xffffffffu, v, o);
        if (lane >= o) v += x;
    }
    if (lane == 31) wsum[wid] = v;
    __syncthreads();
    if (tid == 0) { int a = 0; for (int w = 0; w < 8; ++w) { int x = wsum[w]; wsum[w] = a; a += x; } }
    __syncthreads();
    int run = v - local + wsum[wid];

#pragma unroll
    for (int c = 0; c < 4; ++c) {
        int i = base + c; unsigned u = u4[c];
        bool sel = false;
        if (u > thr) sel = true;
        else if (eqf[c]) { sel = (run < need_eq); run++; }
        if (sel) {
            int p = atomicAdd(&s_cnt, 1);
            if (p < 64) { selid[p] = i; selsc[p] = sc[i]; }
        }
    }
    __syncthreads();
    int cnt = s_cnt; if (cnt > 64) cnt = 64;

    if (tid < 64) {
        float xx = (tid < cnt) ? selsc[tid] : NEG;
#pragma unroll
        for (int o = 16; o; o >>= 1) xx = fmaxf(xx, __shfl_xor_sync(0xffffffffu, xx, o));
        if ((tid & 31) == 0) s_red[tid >> 5] = xx;
    }
    __syncthreads();
    float m = fmaxf(s_red[0], s_red[1]);
    __syncthreads();
    if (tid < 64) {
        float e = (tid < cnt) ? __expf(selsc[tid] - m) : 0.f;
        selw[tid] = e;
#pragma unroll
        for (int o = 16; o; o >>= 1) e += __shfl_xor_sync(0xffffffffu, e, o);
        if ((tid & 31) == 0) s_red[tid >> 5] = e;
    }
    __syncthreads();
    float invZ = 1.f / (s_red[0] + s_red[1]);

    int g = tid >> 6, d = tid & 63;
    float acc = 0.f;
    const float* Vb = g_V + (size_t)bh * T_ * HD;
    for (int p = g; p < cnt; p += 4) acc += selw[p] * Vb[(size_t)selid[p] * HD + d];
    part[tid] = acc;
    __syncthreads();
    if (tid < 64) {
        float o = (part[tid] + part[tid + 64] + part[tid + 128] + part[tid + 192]) * invZ;
        int b = bh >> 4, h = bh & 15;
        g_AO[((size_t)(b * T_ + t)) * DM + h * HD + tid] = o;
    }
}

// ---------------- launch ----------------
extern "C" void kernel_launch(void* const* d_in, const int* in_sizes, int n_in,
                              void* d_out, int out_size) {
    const float* x  = (const float*)d_in[0];
    const float* wq = (const float*)d_in[1];
    const float* wk = (const float*)d_in[2];
    const float* wv = (const float*)d_in[3];
    const float* wo = (const float*)d_in[4];
    float* out = (float*)d_out;

    sgemm_qkv<<<dim3(DM / BN, ROWS / BM, 3), 256>>>(x, wq, wk, wv);

    sparsify_kernel<<<(3 * UNITS) / 8, 256>>>();

    attn_kernel<<<dim3(T_, B_ * NH), 256>>>();

    mma_gemm_o<<<dim3(DM / 128, ROWS / 128, 1), 256>>>(wo, out);
}

// round 13
// speedup vs baseline: 1.0923x; 1.0866x over previous
#include <cuda_runtime.h>
#include <cstdint>

#define B_    4
#define T_    1024
#define DM    1024
#define NH    16
#define HD    64
#define ROWS  (B_ * T_)        // 4096
#define UNITS (ROWS * NH)      // 65536
#define VGUARD 1e-4f

// ---------------- static device scratch (no allocations allowed) ----------------
__device__ float g_Y[3][ROWS * DM];       // raw Q/K/V projections   48 MB
__device__ float g_KT[64 * HD * T_];      // sparsified K, [bh][d][t] 16 MB
__device__ float g_V[UNITS * HD];         // sparsified V 16 MB
__device__ float g_Q4v[UNITS * 4];        // top-4 q values
__device__ int   g_Q4i[UNITS * 4];        // top-4 q indices (ascending)
__device__ float g_AO[ROWS * DM];         // attention output 16 MB
__device__ int   g_FixCount;              // V-units needing exact recompute
__device__ int   g_FixList[4096];

// =================== fp32 FFMA SGEMM (Q,K): double-buffered, padded smem ===================
#define BM  128
#define BN  128
#define BKK 16
#define BMP (BM + 4)                      // pad: STS bank conflicts 4-way -> 2-way, keeps 16B align

__device__ __forceinline__ void sgemm_db_body(const float* __restrict__ X,
                                              const float* __restrict__ W,
                                              float* __restrict__ Y) {
    __shared__ float As[2][BKK][BMP];
    __shared__ float Bs[2][BKK][BMP];
    int tid = threadIdx.x;
    int tx = tid & 15, ty = tid >> 4;
    int m0 = blockIdx.y * BM, n0 = blockIdx.x * BN;

    float acc[8][8];
#pragma unroll
    for (int i = 0; i < 8; ++i)
#pragma unroll
        for (int j = 0; j < 8; ++j) acc[i][j] = 0.f;

    int lr = tid >> 2;   // 0..63
    int lc = tid & 3;    // 0..3

#pragma unroll
    for (int rr = 0; rr < 2; ++rr) {
        int r = lr + rr * 64;
        float4 a = *(const float4*)(X + (size_t)(m0 + r) * DM + lc * 4);
        As[0][lc * 4 + 0][r] = a.x; As[0][lc * 4 + 1][r] = a.y;
        As[0][lc * 4 + 2][r] = a.z; As[0][lc * 4 + 3][r] = a.w;
        float4 b = *(const float4*)(W + (size_t)(n0 + r) * DM + lc * 4);
        Bs[0][lc * 4 + 0][r] = b.x; Bs[0][lc * 4 + 1][r] = b.y;
        Bs[0][lc * 4 + 2][r] = b.z; Bs[0][lc * 4 + 3][r] = b.w;
    }
    __syncthreads();

    for (int c = 0; c < DM / BKK; ++c) {
        int cur = c & 1, nxt = cur ^ 1;
        bool hn = (c + 1) < DM / BKK;
        float4 pa0, pa1, pb0, pb1;
        if (hn) {
            int kn = (c + 1) * BKK;
            pa0 = *(const float4*)(X + (size_t)(m0 + lr) * DM + kn + lc * 4);
            pa1 = *(const float4*)(X + (size_t)(m0 + lr + 64) * DM + kn + lc * 4);
            pb0 = *(const float4*)(W + (size_t)(n0 + lr) * DM + kn + lc * 4);
            pb1 = *(const float4*)(W + (size_t)(n0 + lr + 64) * DM + kn + lc * 4);
        }
#pragma unroll
        for (int kk = 0; kk < BKK; ++kk) {
            float4 a0 = *(const float4*)&As[cur][kk][ty * 8];
            float4 a1 = *(const float4*)&As[cur][kk][ty * 8 + 4];
            float4 b0 = *(const float4*)&Bs[cur][kk][tx * 8];
            float4 b1 = *(const float4*)&Bs[cur][kk][tx * 8 + 4];
            float a[8] = {a0.x, a0.y, a0.z, a0.w, a1.x, a1.y, a1.z, a1.w};
            float b[8] = {b0.x, b0.y, b0.z, b0.w, b1.x, b1.y, b1.z, b1.w};
#pragma unroll
            for (int i = 0; i < 8; ++i)
#pragma unroll
                for (int j = 0; j < 8; ++j) acc[i][j] = fmaf(a[i], b[j], acc[i][j]);
        }
        if (hn) {
            As[nxt][lc * 4 + 0][lr] = pa0.x; As[nxt][lc * 4 + 1][lr] = pa0.y;
            As[nxt][lc * 4 + 2][lr] = pa0.z; As[nxt][lc * 4 + 3][lr] = pa0.w;
            As[nxt][lc * 4 + 0][lr + 64] = pa1.x; As[nxt][lc * 4 + 1][lr + 64] = pa1.y;
            As[nxt][lc * 4 + 2][lr + 64] = pa1.z; As[nxt][lc * 4 + 3][lr + 64] = pa1.w;
            Bs[nxt][lc * 4 + 0][lr] = pb0.x; Bs[nxt][lc * 4 + 1][lr] = pb0.y;
            Bs[nxt][lc * 4 + 2][lr] = pb0.z; Bs[nxt][lc * 4 + 3][lr] = pb0.w;
            Bs[nxt][lc * 4 + 0][lr + 64] = pb1.x; Bs[nxt][lc * 4 + 1][lr + 64] = pb1.y;
            Bs[nxt][lc * 4 + 2][lr + 64] = pb1.z; Bs[nxt][lc * 4 + 3][lr + 64] = pb1.w;
        }
        __syncthreads();
    }
#pragma unroll
    for (int i = 0; i < 8; ++i) {
        float* yp = Y + (size_t)(m0 + ty * 8 + i) * DM + n0 + tx * 8;
        *(float4*)yp = make_float4(acc[i][0], acc[i][1], acc[i][2], acc[i][3]);
        *(float4*)(yp + 4) = make_float4(acc[i][4], acc[i][5], acc[i][6], acc[i][7]);
    }
}

__global__ void __launch_bounds__(256) sgemm_qk(const float* __restrict__ X,
                                                const float* __restrict__ Wq,
                                                const float* __restrict__ Wk) {
    const float* W = (blockIdx.z == 0) ? Wq : Wk;
    sgemm_db_body(X, W, g_Y[blockIdx.z]);
}

// =================== bf16x3 warp-MMA GEMM (V projection + O projection) ===================
#define LDW   12

__device__ __forceinline__ unsigned cvt2(float hi, float lo) {
    unsigned r;
    asm("cvt.rn.bf16x2.f32 %0, %1, %2;" : "=r"(r) : "f"(hi), "f"(lo));
    return r;
}
__device__ __forceinline__ void mma_bf16(float* c, const unsigned* a, const unsigned* b) {
    asm volatile(
        "mma.sync.aligned.m16n8k16.row.col.f32.bf16.bf16.f32 "
        "{%0,%1,%2,%3}, {%4,%5,%6,%7}, {%8,%9}, {%0,%1,%2,%3};"
        : "+f"(c[0]), "+f"(c[1]), "+f"(c[2]), "+f"(c[3])
        : "r"(a[0]), "r"(a[1]), "r"(a[2]), "r"(a[3]), "r"(b[0]), "r"(b[1]));
}

__device__ __forceinline__ void split_store3(unsigned* S0, unsigned* S1, unsigned* S2,
                                             int r, int c4, float4 a) {
    unsigned p0 = cvt2(a.y, a.x);
    float h0 = __uint_as_float(p0 & 0xffff0000u), l0 = __uint_as_float(p0 << 16);
    float rx = a.x - l0, ry = a.y - h0;
    unsigned p1 = cvt2(ry, rx);
    float h1 = __uint_as_float(p1 & 0xffff0000u), l1 = __uint_as_float(p1 << 16);
    unsigned p2 = cvt2(ry - h1, rx - l1);
    unsigned q0 = cvt2(a.w, a.z);
    float h2 = __uint_as_float(q0 & 0xffff0000u), l2 = __uint_as_float(q0 << 16);
    float rz = a.z - l2, rw = a.w - h2;
    unsigned q1 = cvt2(rw, rz);
    float h3 = __uint_as_float(q1 & 0xffff0000u), l3 = __uint_as_float(q1 << 16);
    unsigned q2 = cvt2(rw - h3, rz - l3);
    int o = r * LDW + c4 * 2;
    *(uint2*)&S0[o] = make_uint2(p0, q0);
    *(uint2*)&S1[o] = make_uint2(p1, q1);
    *(uint2*)&S2[o] = make_uint2(p2, q2);
}

__device__ __forceinline__ void mma3_body(const float* __restrict__ X,
                                          const float* __restrict__ W,
                                          float* __restrict__ Y) {
    __shared__ unsigned A0s[128 * LDW], A1s[128 * LDW], A2s[128 * LDW];
    __shared__ unsigned B0s[128 * LDW], B1s[128 * LDW], B2s[128 * LDW];
    int tid = threadIdx.x, lane = tid & 31, wid = tid >> 5;
    int m0 = blockIdx.y * 128, n0 = blockIdx.x * 128;
    int wm = (wid >> 2) * 64, wn = (wid & 3) * 32;
    int gid = lane >> 2, tig = lane & 3;

    float acc[4][4][4];
#pragma unroll
    for (int i = 0; i < 4; ++i)
#pragma unroll
        for (int j = 0; j < 4; ++j)
#pragma unroll
            for (int q = 0; q < 4; ++q) acc[i][j][q] = 0.f;

    int lr = tid >> 2, lc4 = tid & 3;

#pragma unroll
    for (int i = 0; i < 2; ++i) {
        int r = lr + i * 64;
        split_store3(A0s, A1s, A2s, r, lc4, *(const float4*)(X + (size_t)(m0 + r) * DM + lc4 * 4));
        split_store3(B0s, B1s, B2s, r, lc4, *(const float4*)(W + (size_t)(n0 + r) * DM + lc4 * 4));
    }
    __syncthreads();

    for (int c = 0; c < DM / 16; ++c) {
        float4 pa[2], pb[2];
        bool has_next = (c + 1) < DM / 16;
        if (has_next) {
            int kn = (c + 1) * 16;
#pragma unroll
            for (int i = 0; i < 2; ++i) {
                int r = lr + i * 64;
                pa[i] = *(const float4*)(X + (size_t)(m0 + r) * DM + kn + lc4 * 4);
                pb[i] = *(const float4*)(W + (size_t)(n0 + r) * DM + kn + lc4 * 4);
            }
        }
        {
            unsigned b0[4][2], b1[4][2], b2[4][2];
#pragma unroll
            for (int j = 0; j < 4; ++j) {
                int nn = (wn + j * 8 + gid) * LDW;
                b0[j][0] = B0s[nn + tig]; b0[j][1] = B0s[nn + tig + 4];
                b1[j][0] = B1s[nn + tig]; b1[j][1] = B1s[nn + tig + 4];
                b2[j][0] = B2s[nn + tig]; b2[j][1] = B2s[nn + tig + 4];
            }
            unsigned af[4][4];
#pragma unroll
            for (int i = 0; i < 4; ++i) {
                int r0 = (wm + i * 16 + gid) * LDW, r1 = r0 + 8 * LDW;
                af[i][0] = A0s[r0 + tig]; af[i][1] = A0s[r1 + tig];
                af[i][2] = A0s[r0 + tig + 4]; af[i][3] = A0s[r1 + tig + 4];
            }
#pragma unroll
            for (int i = 0; i < 4; ++i)
#pragma unroll
                for (int j = 0; j < 4; ++j) {
                    mma_bf16(acc[i][j], af[i], b0[j]);
                    mma_bf16(acc[i][j], af[i], b1[j]);
                    mma_bf16(acc[i][j], af[i], b2[j]);
                }
#pragma unroll
            for (int i = 0; i < 4; ++i) {
                int r0 = (wm + i * 16 + gid) * LDW, r1 = r0 + 8 * LDW;
                af[i][0] = A1s[r0 + tig]; af[i][1] = A1s[r1 + tig];
                af[i][2] = A1s[r0 + tig + 4]; af[i][3] = A1s[r1 + tig + 4];
            }
#pragma unroll
            for (int i = 0; i < 4; ++i)
#pragma unroll
                for (int j = 0; j < 4; ++j) {
                    mma_bf16(acc[i][j], af[i], b0[j]);
                    mma_bf16(acc[i][j], af[i], b1[j]);
                }
#pragma unroll
            for (int i = 0; i < 4; ++i) {
                int r0 = (wm + i * 16 + gid) * LDW, r1 = r0 + 8 * LDW;
                af[i][0] = A2s[r0 + tig]; af[i][1] = A2s[r1 + tig];
                af[i][2] = A2s[r0 + tig + 4]; af[i][3] = A2s[r1 + tig + 4];
            }
#pragma unroll
            for (int i = 0; i < 4; ++i)
#pragma unroll
                for (int j = 0; j < 4; ++j)
                    mma_bf16(acc[i][j], af[i], b0[j]);
        }
        __syncthreads();
        if (has_next) {
#pragma unroll
            for (int i = 0; i < 2; ++i) {
                int r = lr + i * 64;
                split_store3(A0s, A1s, A2s, r, lc4, pa[i]);
                split_store3(B0s, B1s, B2s, r, lc4, pb[i]);
            }
            __syncthreads();
        }
    }

#pragma unroll
    for (int i = 0; i < 4; ++i) {
        int r0 = m0 + wm + i * 16 + gid, r1 = r0 + 8;
#pragma unroll
        for (int j = 0; j < 4; ++j) {
            int cb = n0 + wn + j * 8 + 2 * tig;
            *(float2*)(Y + (size_t)r0 * DM + cb) = make_float2(acc[i][j][0], acc[i][j][1]);
            *(float2*)(Y + (size_t)r1 * DM + cb) = make_float2(acc[i][j][2], acc[i][j][3]);
        }
    }
}

__global__ void __launch_bounds__(256, 2) mma_gemm_v(const float* __restrict__ X,
                                                     const float* __restrict__ Wv) {
    if (blockIdx.x == 0 && blockIdx.y == 0 && threadIdx.x == 0) g_FixCount = 0;
    mma3_body(X, Wv, g_Y[2]);
}
__global__ void __launch_bounds__(256, 2) mma_gemm_o(const float* __restrict__ Wo,
                                                     float* __restrict__ Y) {
    mma3_body(g_AO, Wo, Y);
}

// ---------------- sparsify: per (b,h,t) keep top-4 by |v| (tie -> lower index) ----------------
// For tensor==2 (V, tensor-core values): also compute 5th-largest |v|; if the 4th/5th gap
// is below VGUARD, flag the unit for exact fp32 recompute (vfix_kernel).
__global__ void __launch_bounds__(256) sparsify_kernel() {
    int warp = (blockIdx.x * blockDim.x + threadIdx.x) >> 5;
    int lane = threadIdx.x & 31;
    int tensor = warp / UNITS;            // 0=q 1=k 2=v
    int idx = warp - tensor * UNITS;
    int row = idx >> 4;                   // b*T + t
    int h = idx & 15;

    const float* Y = g_Y[tensor];
    float v0 = Y[(size_t)row * DM + h * HD + lane];
    float v1 = Y[(size_t)row * DM + h * HD + 32 + lane];
    unsigned a0 = __float_as_uint(v0) & 0x7fffffffu;
    unsigned a1 = __float_as_uint(v1) & 0x7fffffffu;
    unsigned long long k0 = ((unsigned long long)a0 << 32) | (unsigned)(63 - lane);
    unsigned long long k1 = ((unsigned long long)a1 << 32) | (unsigned)(31 - lane);

    bool s0 = false, s1 = false;
    int selD[4]; float selV[4];
    float abs4 = 0.f, abs5 = 0.f;
    int rounds = (tensor == 2) ? 5 : 4;
    for (int r = 0; r < rounds; ++r) {
        unsigned long long m = (k0 > k1) ? k0 : k1;
#pragma unroll
        for (int o = 16; o; o >>= 1) {
            unsigned long long t2 = __shfl_xor_sync(0xffffffffu, m, o);
            if (t2 > m) m = t2;
        }
        if (r < 4) {
            int d = 63 - (int)(unsigned)(m & 0xffffffffULL);
            selD[r] = d;
            float srcv = (d < 32) ? v0 : v1;
            selV[r] = __shfl_sync(0xffffffffu, srcv, d & 31);
            if (d < 32) { if (lane == d) { k0 = 0; s0 = true; } }
            else        { if (lane == (d - 32)) { k1 = 0; s1 = true; } }
            if (r == 3) abs4 = __uint_as_float((unsigned)(m >> 32));
        } else {
            abs5 = __uint_as_float((unsigned)(m >> 32));
        }
    }

    int b = row >> 10, t = row & (T_ - 1);
    int bh = b * NH + h;

    if (tensor == 0) {
        if (lane == 0) {
#pragma unroll
            for (int a = 0; a < 3; ++a)
#pragma unroll
                for (int c = 0; c < 3; ++c)
                    if (selD[c + 1] < selD[c]) {
                        int td = selD[c]; selD[c] = selD[c + 1]; selD[c + 1] = td;
                        float tv = selV[c]; selV[c] = selV[c + 1]; selV[c + 1] = tv;
                    }
            size_t base = ((size_t)bh * T_ + t) * 4;
#pragma unroll
            for (int r = 0; r < 4; ++r) { g_Q4i[base + r] = selD[r]; g_Q4v[base + r] = selV[r]; }
        }
    } else if (tensor == 1) {
        g_KT[((size_t)bh * HD + lane) * T_ + t]      = s0 ? v0 : 0.f;
        g_KT[((size_t)bh * HD + 32 + lane) * T_ + t] = s1 ? v1 : 0.f;
    } else {
        g_V[((size_t)bh * T_ + t) * HD + lane]      = s0 ? v0 : 0.f;
        g_V[((size_t)bh * T_ + t) * HD + 32 + lane] = s1 ? v1 : 0.f;
        if (lane == 0 && (abs4 - abs5) < VGUARD) {
            int p = atomicAdd(&g_FixCount, 1);
            if (p < 4096) g_FixList[p] = (bh << 10) | t;
        }
    }
}

// ---------------- vfix: exact fp32 recompute + reselect for guarded V units ----------------
__global__ void __launch_bounds__(64) vfix_kernel(const float* __restrict__ x,
                                                  const float* __restrict__ wv) {
    __shared__ float vals[64];
    __shared__ int   selm[64];
    int cnt = g_FixCount; if (cnt > 4096) cnt = 4096;
    for (int i = blockIdx.x; i < cnt; i += gridDim.x) {
        int unit = g_FixList[i];
        int bh = unit >> 10, t = unit & (T_ - 1);
        int b = bh >> 4, h = bh & 15;
        int row = b * T_ + t;
        int f = threadIdx.x;
        const float4* xr = (const float4*)(x + (size_t)row * DM);
        const float4* wr = (const float4*)(wv + (size_t)(h * HD + f) * DM);
        float acc = 0.f;
        for (int k = 0; k < DM / 4; ++k) {
            float4 a = xr[k], w = wr[k];
            acc += a.x * w.x; acc += a.y * w.y; acc += a.z * w.z; acc += a.w * w.w;
        }
        vals[f] = acc;
        __syncthreads();
        if (f < 32) {
            int lane = f;
            float v0 = vals[lane], v1 = vals[lane + 32];
            unsigned a0 = __float_as_uint(v0) & 0x7fffffffu;
            unsigned a1 = __float_as_uint(v1) & 0x7fffffffu;
            unsigned long long k0 = ((unsigned long long)a0 << 32) | (unsigned)(63 - lane);
            unsigned long long k1 = ((unsigned long long)a1 << 32) | (unsigned)(31 - lane);
            bool s0 = false, s1 = false;
#pragma unroll
            for (int r = 0; r < 4; ++r) {
                unsigned long long m = (k0 > k1) ? k0 : k1;
#pragma unroll
                for (int o = 16; o; o >>= 1) {
                    unsigned long long t2 = __shfl_xor_sync(0xffffffffu, m, o);
                    if (t2 > m) m = t2;
                }
                int d = 63 - (int)(unsigned)(m & 0xffffffffULL);
                if (d < 32) { if (lane == d) { k0 = 0; s0 = true; } }
                else        { if (lane == (d - 32)) { k1 = 0; s1 = true; } }
            }
            selm[lane] = s0 ? 1 : 0;
            selm[lane + 32] = s1 ? 1 : 0;
        }
        __syncthreads();
        g_V[((size_t)bh * T_ + t) * HD + f] = selm[f] ? vals[f] : 0.f;
        __syncthreads();
    }
}

// ---------------- attention: proven block-radix top-64 (round-9 version) ----------------
__global__ void __launch_bounds__(256) attn_kernel() {
    int t  = blockIdx.x;
    int bh = blockIdx.y;
    int tid = threadIdx.x;
    int lane = tid & 31, wid = tid >> 5;

    __shared__ float    sc[T_];
    __shared__ unsigned su[T_];
    __shared__ int      hist[256];
    __shared__ int      candA[T_], candB[T_];
    __shared__ int      s_bin, s_remsh, s_C, s_cnt;
    __shared__ float    s_red[2];
    __shared__ int      selid[64];
    __shared__ float    selsc[64], selw[64];
    __shared__ int      wsum[8];
    __shared__ int      cls_sum[8];
    __shared__ float    part[256];
    __shared__ int      qidx[4];
    __shared__ float    qval[4];

    if (tid == 0) s_cnt = 0;
    if (tid < 4) {
        size_t qb = ((size_t)bh * T_ + t) * 4 + tid;
        qidx[tid] = g_Q4i[qb];
        qval[tid] = g_Q4v[qb];
    }
    __syncthreads();

    const float NEG = __int_as_float(0xff800000);
    const float* K0 = g_KT + ((size_t)bh * HD + qidx[0]) * T_;
    const float* K1 = g_KT + ((size_t)bh * HD + qidx[1]) * T_;
    const float* K2 = g_KT + ((size_t)bh * HD + qidx[2]) * T_;
    const float* K3 = g_KT + ((size_t)bh * HD + qidx[3]) * T_;
    float q0 = qval[0], q1 = qval[1], q2 = qval[2], q3 = qval[3];

    int n = t + 1;
#pragma unroll
    for (int r = 0; r < 4; ++r) {
        int i = tid + r * 256;
        unsigned u = 0u;
        if (i < n) {
            float s = (q0 * K0[i] + q1 * K1[i] + q2 * K2[i] + q3 * K3[i]) * 0.125f;
            sc[i] = s;
            unsigned bits = __float_as_uint(s);
            if (bits == 0x80000000u) bits = 0u;
            u = (bits & 0x80000000u) ? ~bits : (bits | 0x80000000u);
        }
        su[i] = u;
    }
    __syncthreads();

    int base = tid * 4;
    unsigned u4[4];
    int pl = 0, zl = 0;
#pragma unroll
    for (int c = 0; c < 4; ++c) {
        u4[c] = su[base + c];
        pl += (u4[c] > 0x80000000u);
        zl += (u4[c] == 0x80000000u);
    }
    int packedc = pl | (zl << 16);
#pragma unroll
    for (int o = 16; o; o >>= 1) packedc += __shfl_xor_sync(0xffffffffu, packedc, o);
    if (lane == 0) cls_sum[wid] = packedc;
    __syncthreads();
    int tot = 0;
#pragma unroll
    for (int w = 0; w < 8; ++w) tot += cls_sum[w];
    int P = tot & 0xffff, Z = tot >> 16;

    unsigned thr = 0u; int need_eq = 0;
    if (n <= 64) {
        thr = 0u; need_eq = 0;
    } else if (P < 64 && P + Z >= 64) {
        thr = 0x80000000u; need_eq = 64 - P;
    } else {
        bool wantPos = (P >= 64);
        if (tid == 0) s_C = 0;
        __syncthreads();
#pragma unroll
        for (int c = 0; c < 4; ++c) {
            int i = base + c;
            bool take = wantPos ? (u4[c] > 0x80000000u) : (i < n);
            unsigned m = __ballot_sync(0xffffffffu, take);
            int cw = __popc(m);
            int pos = __popc(m & ((1u << lane) - 1u));
            int wb = 0;
            if (lane == 0 && cw) wb = atomicAdd(&s_C, cw);
            wb = __shfl_sync(0xffffffffu, wb, 0);
            if (take) candA[wb + pos] = i;
        }
        __syncthreads();
        int C = s_C;
        __syncthreads();
        int rem = 64;
        unsigned pref = 0u;
        int* cur = candA; int* nxt = candB;
        bool fullkey = true;
        for (int shift = 24; shift >= 0; shift -= 8) {
            if (C == 1) { fullkey = false; break; }
            hist[tid] = 0;
            if (tid == 0) s_C = 0;
            __syncthreads();
            int rounds = (C + 255) >> 8;
            for (int r = 0; r < rounds; ++r) {
                int j = r * 256 + tid;
                int b = (j < C) ? (int)((su[cur[j]] >> shift) & 255u) : -1;
                unsigned m = __match_any_sync(0xffffffffu, b);
                if (b >= 0 && (int)__ffs(m) - 1 == lane) atomicAdd(&hist[b], __popc(m));
            }
            __syncthreads();
            if (wid == 0) {
                int bs = lane * 8;
                int loc[8]; int ssum = 0;
#pragma unroll
                for (int k = 7; k >= 0; --k) { ssum += hist[bs + k]; loc[k] = ssum; }
                int g = ssum;
#pragma unroll
                for (int off = 1; off < 32; off <<= 1) {
                    int v = __shfl_down_sync(0xffffffffu, g, off);
                    if (lane + off < 32) g += v;
                }
                int Hh = g - ssum;
#pragma unroll
                for (int k = 7; k >= 0; --k) {
                    int suf = loc[k] + Hh;
                    int nx2 = (k == 7) ? Hh : (loc[k + 1] + Hh);
                    if (suf >= rem && nx2 < rem) { s_bin = bs + k; s_remsh = rem - nx2; }
                }
            }
            __syncthreads();
            int b2 = s_bin; rem = s_remsh;
            int rounds2 = (C + 255) >> 8;
            for (int r = 0; r < rounds2; ++r) {
                int j = r * 256 + tid;
                if (j < C && (int)((su[cur[j]] >> shift) & 255u) == b2) {
                    int p = atomicAdd(&s_C, 1); nxt[p] = cur[j];
                }
            }
            __syncthreads();
            C = s_C;
            __syncthreads();
            pref |= (unsigned)b2 << shift;
            int* tsw = cur; cur = nxt; nxt = tsw;
        }
        thr = fullkey ? pref : su[cur[0]];
        need_eq = rem;
    }

    int eqf[4]; int local = 0;
#pragma unroll
    for (int c = 0; c < 4; ++c) { eqf[c] = (u4[c] == thr) ? 1 : 0; local += eqf[c]; }
    int v = local;
#pragma unroll
    for (int o = 1; o < 32; o <<= 1) {
        int x = __shfl_up_sync(0xffffffffu, v, o);
        if (lane >= o) v += x;
    }
    if (lane == 31) wsum[wid] = v;
    __syncthreads();
    if (tid == 0) { int a = 0; for (int w = 0; w < 8; ++w) { int x = wsum[w]; wsum[w] = a; a += x; } }
    __syncthreads();
    int run = v - local + wsum[wid];

#pragma unroll
    for (int c = 0; c < 4; ++c) {
        int i = base + c; unsigned u = u4[c];
        bool sel = false;
        if (u > thr) sel = true;
        else if (eqf[c]) { sel = (run < need_eq); run++; }
        if (sel) {
            int p = atomicAdd(&s_cnt, 1);
            if (p < 64) { selid[p] = i; selsc[p] = sc[i]; }
        }
    }
    __syncthreads();
    int cnt = s_cnt; if (cnt > 64) cnt = 64;

    if (tid < 64) {
        float xx = (tid < cnt) ? selsc[tid] : NEG;
#pragma unroll
        for (int o = 16; o; o >>= 1) xx = fmaxf(xx, __shfl_xor_sync(0xffffffffu, xx, o));
        if ((tid & 31) == 0) s_red[tid >> 5] = xx;
    }
    __syncthreads();
    float m = fmaxf(s_red[0], s_red[1]);
    __syncthreads();
    if (tid < 64) {
        float e = (tid < cnt) ? __expf(selsc[tid] - m) : 0.f;
        selw[tid] = e;
#pragma unroll
        for (int o = 16; o; o >>= 1) e += __shfl_xor_sync(0xffffffffu, e, o);
        if ((tid & 31) == 0) s_red[tid >> 5] = e;
    }
    __syncthreads();
    float invZ = 1.f / (s_red[0] + s_red[1]);

    int g = tid >> 6, d = tid & 63;
    float acc = 0.f;
    const float* Vb = g_V + (size_t)bh * T_ * HD;
    for (int p = g; p < cnt; p += 4) acc += selw[p] * Vb[(size_t)selid[p] * HD + d];
    part[tid] = acc;
    __syncthreads();
    if (tid < 64) {
        float o = (part[tid] + part[tid + 64] + part[tid + 128] + part[tid + 192]) * invZ;
        int b = bh >> 4, h = bh & 15;
        g_AO[((size_t)(b * T_ + t)) * DM + h * HD + tid] = o;
    }
}

// ---------------- launch ----------------
extern "C" void kernel_launch(void* const* d_in, const int* in_sizes, int n_in,
                              void* d_out, int out_size) {
    const float* x  = (const float*)d_in[0];
    const float* wq = (const float*)d_in[1];
    const float* wk = (const float*)d_in[2];
    const float* wv = (const float*)d_in[3];
    const float* wo = (const float*)d_in[4];
    float* out = (float*)d_out;

    sgemm_qk<<<dim3(DM / BN, ROWS / BM, 2), 256>>>(x, wq, wk);

    mma_gemm_v<<<dim3(DM / 128, ROWS / 128), 256>>>(x, wv);

    sparsify_kernel<<<(3 * UNITS) / 8, 256>>>();

    vfix_kernel<<<256, 64>>>(x, wv);

    attn_kernel<<<dim3(T_, B_ * NH), 256>>>();

    mma_gemm_o<<<dim3(DM / 128, ROWS / 128), 256>>>(wo, out);
}

// round 14
// speedup vs baseline: 1.1579x; 1.0601x over previous
#include <cuda_runtime.h>
#include <cstdint>

#define B_    4
#define T_    1024
#define DM    1024
#define NH    16
#define HD    64
#define ROWS  (B_ * T_)        // 4096
#define UNITS (ROWS * NH)      // 65536
#define VGUARD 1e-4f

// ---------------- static device scratch (no allocations allowed) ----------------
__device__ float g_Y[3][ROWS * DM];       // raw Q/K/V projections   48 MB
__device__ float g_KT[64 * HD * T_];      // sparsified K, [bh][d][t] 16 MB
__device__ float g_V[UNITS * HD];         // sparsified V 16 MB
__device__ float g_Q4v[UNITS * 4];        // top-4 q values
__device__ int   g_Q4i[UNITS * 4];        // top-4 q indices (ascending)
__device__ float g_AO[ROWS * DM];         // attention output 16 MB
__device__ int   g_FixCount;              // V-units needing exact recompute
__device__ int   g_FixList[4096];

// =================== fp32 FFMA SGEMM (Q,K): conflict-free fragment mapping ===================
// Thread (tx,ty) owns rows {ty*4..+3, 64+ty*4..+3} x cols {tx*4..+3, 64+tx*4..+3}:
// fragment LDS.128 are 16B-strided (contiguous per 8-lane phase) -> zero bank conflicts.
#define BM  128
#define BN  128
#define BKK 16
#define BMP (BM + 4)

__device__ __forceinline__ void sgemm_db_body(const float* __restrict__ X,
                                              const float* __restrict__ W,
                                              float* __restrict__ Y) {
    __shared__ float As[2][BKK][BMP];
    __shared__ float Bs[2][BKK][BMP];
    int tid = threadIdx.x;
    int tx = tid & 15, ty = tid >> 4;
    int m0 = blockIdx.y * BM, n0 = blockIdx.x * BN;

    float acc[8][8];
#pragma unroll
    for (int i = 0; i < 8; ++i)
#pragma unroll
        for (int j = 0; j < 8; ++j) acc[i][j] = 0.f;

    int lr = tid >> 2;   // 0..63
    int lc = tid & 3;    // 0..3

#pragma unroll
    for (int rr = 0; rr < 2; ++rr) {
        int r = lr + rr * 64;
        float4 a = *(const float4*)(X + (size_t)(m0 + r) * DM + lc * 4);
        As[0][lc * 4 + 0][r] = a.x; As[0][lc * 4 + 1][r] = a.y;
        As[0][lc * 4 + 2][r] = a.z; As[0][lc * 4 + 3][r] = a.w;
        float4 b = *(const float4*)(W + (size_t)(n0 + r) * DM + lc * 4);
        Bs[0][lc * 4 + 0][r] = b.x; Bs[0][lc * 4 + 1][r] = b.y;
        Bs[0][lc * 4 + 2][r] = b.z; Bs[0][lc * 4 + 3][r] = b.w;
    }
    __syncthreads();

    for (int c = 0; c < DM / BKK; ++c) {
        int cur = c & 1, nxt = cur ^ 1;
        bool hn = (c + 1) < DM / BKK;
        float4 pa0, pa1, pb0, pb1;
        if (hn) {
            int kn = (c + 1) * BKK;
            pa0 = *(const float4*)(X + (size_t)(m0 + lr) * DM + kn + lc * 4);
            pa1 = *(const float4*)(X + (size_t)(m0 + lr + 64) * DM + kn + lc * 4);
            pb0 = *(const float4*)(W + (size_t)(n0 + lr) * DM + kn + lc * 4);
            pb1 = *(const float4*)(W + (size_t)(n0 + lr + 64) * DM + kn + lc * 4);
        }
#pragma unroll
        for (int kk = 0; kk < BKK; ++kk) {
            float4 a0 = *(const float4*)&As[cur][kk][ty * 4];
            float4 a1 = *(const float4*)&As[cur][kk][64 + ty * 4];
            float4 b0 = *(const float4*)&Bs[cur][kk][tx * 4];
            float4 b1 = *(const float4*)&Bs[cur][kk][64 + tx * 4];
            float a[8] = {a0.x, a0.y, a0.z, a0.w, a1.x, a1.y, a1.z, a1.w};
            float b[8] = {b0.x, b0.y, b0.z, b0.w, b1.x, b1.y, b1.z, b1.w};
#pragma unroll
            for (int i = 0; i < 8; ++i)
#pragma unroll
                for (int j = 0; j < 8; ++j) acc[i][j] = fmaf(a[i], b[j], acc[i][j]);
        }
        if (hn) {
            As[nxt][lc * 4 + 0][lr] = pa0.x; As[nxt][lc * 4 + 1][lr] = pa0.y;
            As[nxt][lc * 4 + 2][lr] = pa0.z; As[nxt][lc * 4 + 3][lr] = pa0.w;
            As[nxt][lc * 4 + 0][lr + 64] = pa1.x; As[nxt][lc * 4 + 1][lr + 64] = pa1.y;
            As[nxt][lc * 4 + 2][lr + 64] = pa1.z; As[nxt][lc * 4 + 3][lr + 64] = pa1.w;
            Bs[nxt][lc * 4 + 0][lr] = pb0.x; Bs[nxt][lc * 4 + 1][lr] = pb0.y;
            Bs[nxt][lc * 4 + 2][lr] = pb0.z; Bs[nxt][lc * 4 + 3][lr] = pb0.w;
            Bs[nxt][lc * 4 + 0][lr + 64] = pb1.x; Bs[nxt][lc * 4 + 1][lr + 64] = pb1.y;
            Bs[nxt][lc * 4 + 2][lr + 64] = pb1.z; Bs[nxt][lc * 4 + 3][lr + 64] = pb1.w;
        }
        __syncthreads();
    }
#pragma unroll
    for (int i = 0; i < 8; ++i) {
        int r = m0 + ((i < 4) ? (ty * 4 + i) : (64 + ty * 4 + (i - 4)));
        float* yp = Y + (size_t)r * DM + n0;
        *(float4*)(yp + tx * 4) = make_float4(acc[i][0], acc[i][1], acc[i][2], acc[i][3]);
        *(float4*)(yp + 64 + tx * 4) = make_float4(acc[i][4], acc[i][5], acc[i][6], acc[i][7]);
    }
}

__global__ void __launch_bounds__(256) sgemm_qk(const float* __restrict__ X,
                                                const float* __restrict__ Wq,
                                                const float* __restrict__ Wk) {
    const float* W = (blockIdx.z == 0) ? Wq : Wk;
    sgemm_db_body(X, W, g_Y[blockIdx.z]);
}

// =================== bf16x3 warp-MMA GEMM (V projection + O projection) ===================
#define LDW   12

__device__ __forceinline__ unsigned cvt2(float hi, float lo) {
    unsigned r;
    asm("cvt.rn.bf16x2.f32 %0, %1, %2;" : "=r"(r) : "f"(hi), "f"(lo));
    return r;
}
__device__ __forceinline__ void mma_bf16(float* c, const unsigned* a, const unsigned* b) {
    asm volatile(
        "mma.sync.aligned.m16n8k16.row.col.f32.bf16.bf16.f32 "
        "{%0,%1,%2,%3}, {%4,%5,%6,%7}, {%8,%9}, {%0,%1,%2,%3};"
        : "+f"(c[0]), "+f"(c[1]), "+f"(c[2]), "+f"(c[3])
        : "r"(a[0]), "r"(a[1]), "r"(a[2]), "r"(a[3]), "r"(b[0]), "r"(b[1]));
}

__device__ __forceinline__ void split_store3(unsigned* S0, unsigned* S1, unsigned* S2,
                                             int r, int c4, float4 a) {
    unsigned p0 = cvt2(a.y, a.x);
    float h0 = __uint_as_float(p0 & 0xffff0000u), l0 = __uint_as_float(p0 << 16);
    float rx = a.x - l0, ry = a.y - h0;
    unsigned p1 = cvt2(ry, rx);
    float h1 = __uint_as_float(p1 & 0xffff0000u), l1 = __uint_as_float(p1 << 16);
    unsigned p2 = cvt2(ry - h1, rx - l1);
    unsigned q0 = cvt2(a.w, a.z);
    float h2 = __uint_as_float(q0 & 0xffff0000u), l2 = __uint_as_float(q0 << 16);
    float rz = a.z - l2, rw = a.w - h2;
    unsigned q1 = cvt2(rw, rz);
    float h3 = __uint_as_float(q1 & 0xffff0000u), l3 = __uint_as_float(q1 << 16);
    unsigned q2 = cvt2(rw - h3, rz - l3);
    int o = r * LDW + c4 * 2;
    *(uint2*)&S0[o] = make_uint2(p0, q0);
    *(uint2*)&S1[o] = make_uint2(p1, q1);
    *(uint2*)&S2[o] = make_uint2(p2, q2);
}

__device__ __forceinline__ void mma3_body(const float* __restrict__ X,
                                          const float* __restrict__ W,
                                          float* __restrict__ Y) {
    __shared__ unsigned A0s[128 * LDW], A1s[128 * LDW], A2s[128 * LDW];
    __shared__ unsigned B0s[128 * LDW], B1s[128 * LDW], B2s[128 * LDW];
    int tid = threadIdx.x, lane = tid & 31, wid = tid >> 5;
    int m0 = blockIdx.y * 128, n0 = blockIdx.x * 128;
    int wm = (wid >> 2) * 64, wn = (wid & 3) * 32;
    int gid = lane >> 2, tig = lane & 3;

    float acc[4][4][4];
#pragma unroll
    for (int i = 0; i < 4; ++i)
#pragma unroll
        for (int j = 0; j < 4; ++j)
#pragma unroll
            for (int q = 0; q < 4; ++q) acc[i][j][q] = 0.f;

    int lr = tid >> 2, lc4 = tid & 3;

#pragma unroll
    for (int i = 0; i < 2; ++i) {
        int r = lr + i * 64;
        split_store3(A0s, A1s, A2s, r, lc4, *(const float4*)(X + (size_t)(m0 + r) * DM + lc4 * 4));
        split_store3(B0s, B1s, B2s, r, lc4, *(const float4*)(W + (size_t)(n0 + r) * DM + lc4 * 4));
    }
    __syncthreads();

    for (int c = 0; c < DM / 16; ++c) {
        float4 pa[2], pb[2];
        bool has_next = (c + 1) < DM / 16;
        if (has_next) {
            int kn = (c + 1) * 16;
#pragma unroll
            for (int i = 0; i < 2; ++i) {
                int r = lr + i * 64;
                pa[i] = *(const float4*)(X + (size_t)(m0 + r) * DM + kn + lc4 * 4);
                pb[i] = *(const float4*)(W + (size_t)(n0 + r) * DM + kn + lc4 * 4);
            }
        }
        {
            unsigned b0[4][2], b1[4][2], b2[4][2];
#pragma unroll
            for (int j = 0; j < 4; ++j) {
                int nn = (wn + j * 8 + gid) * LDW;
                b0[j][0] = B0s[nn + tig]; b0[j][1] = B0s[nn + tig + 4];
                b1[j][0] = B1s[nn + tig]; b1[j][1] = B1s[nn + tig + 4];
                b2[j][0] = B2s[nn + tig]; b2[j][1] = B2s[nn + tig + 4];
            }
            unsigned af[4][4];
#pragma unroll
            for (int i = 0; i < 4; ++i) {
                int r0 = (wm + i * 16 + gid) * LDW, r1 = r0 + 8 * LDW;
                af[i][0] = A0s[r0 + tig]; af[i][1] = A0s[r1 + tig];
                af[i][2] = A0s[r0 + tig + 4]; af[i][3] = A0s[r1 + tig + 4];
            }
#pragma unroll
            for (int i = 0; i < 4; ++i)
#pragma unroll
                for (int j = 0; j < 4; ++j) {
                    mma_bf16(acc[i][j], af[i], b0[j]);
                    mma_bf16(acc[i][j], af[i], b1[j]);
                    mma_bf16(acc[i][j], af[i], b2[j]);
                }
#pragma unroll
            for (int i = 0; i < 4; ++i) {
                int r0 = (wm + i * 16 + gid) * LDW, r1 = r0 + 8 * LDW;
                af[i][0] = A1s[r0 + tig]; af[i][1] = A1s[r1 + tig];
                af[i][2] = A1s[r0 + tig + 4]; af[i][3] = A1s[r1 + tig + 4];
            }
#pragma unroll
            for (int i = 0; i < 4; ++i)
#pragma unroll
                for (int j = 0; j < 4; ++j) {
                    mma_bf16(acc[i][j], af[i], b0[j]);
                    mma_bf16(acc[i][j], af[i], b1[j]);
                }
#pragma unroll
            for (int i = 0; i < 4; ++i) {
                int r0 = (wm + i * 16 + gid) * LDW, r1 = r0 + 8 * LDW;
                af[i][0] = A2s[r0 + tig]; af[i][1] = A2s[r1 + tig];
                af[i][2] = A2s[r0 + tig + 4]; af[i][3] = A2s[r1 + tig + 4];
            }
#pragma unroll
            for (int i = 0; i < 4; ++i)
#pragma unroll
                for (int j = 0; j < 4; ++j)
                    mma_bf16(acc[i][j], af[i], b0[j]);
        }
        __syncthreads();
        if (has_next) {
#pragma unroll
            for (int i = 0; i < 2; ++i) {
                int r = lr + i * 64;
                split_store3(A0s, A1s, A2s, r, lc4, pa[i]);
                split_store3(B0s, B1s, B2s, r, lc4, pb[i]);
            }
            __syncthreads();
        }
    }

#pragma unroll
    for (int i = 0; i < 4; ++i) {
        int r0 = m0 + wm + i * 16 + gid, r1 = r0 + 8;
#pragma unroll
        for (int j = 0; j < 4; ++j) {
            int cb = n0 + wn + j * 8 + 2 * tig;
            *(float2*)(Y + (size_t)r0 * DM + cb) = make_float2(acc[i][j][0], acc[i][j][1]);
            *(float2*)(Y + (size_t)r1 * DM + cb) = make_float2(acc[i][j][2], acc[i][j][3]);
        }
    }
}

__global__ void __launch_bounds__(256, 2) mma_gemm_v(const float* __restrict__ X,
                                                     const float* __restrict__ Wv) {
    if (blockIdx.x == 0 && blockIdx.y == 0 && threadIdx.x == 0) g_FixCount = 0;
    mma3_body(X, Wv, g_Y[2]);
}
__global__ void __launch_bounds__(256, 2) mma_gemm_o(const float* __restrict__ Wo,
                                                     float* __restrict__ Y) {
    mma3_body(g_AO, Wo, Y);
}

// ---------------- sparsify: per (b,h,t) keep top-4 by |v| (tie -> lower index) ----------------
__global__ void __launch_bounds__(256) sparsify_kernel() {
    int warp = (blockIdx.x * blockDim.x + threadIdx.x) >> 5;
    int lane = threadIdx.x & 31;
    int tensor = warp / UNITS;            // 0=q 1=k 2=v
    int idx = warp - tensor * UNITS;
    int row = idx >> 4;                   // b*T + t
    int h = idx & 15;

    const float* Y = g_Y[tensor];
    float v0 = Y[(size_t)row * DM + h * HD + lane];
    float v1 = Y[(size_t)row * DM + h * HD + 32 + lane];
    unsigned a0 = __float_as_uint(v0) & 0x7fffffffu;
    unsigned a1 = __float_as_uint(v1) & 0x7fffffffu;
    unsigned long long k0 = ((unsigned long long)a0 << 32) | (unsigned)(63 - lane);
    unsigned long long k1 = ((unsigned long long)a1 << 32) | (unsigned)(31 - lane);

    bool s0 = false, s1 = false;
    int selD[4]; float selV[4];
    float abs4 = 0.f, abs5 = 0.f;
    int rounds = (tensor == 2) ? 5 : 4;
    for (int r = 0; r < rounds; ++r) {
        unsigned long long m = (k0 > k1) ? k0 : k1;
#pragma unroll
        for (int o = 16; o; o >>= 1) {
            unsigned long long t2 = __shfl_xor_sync(0xffffffffu, m, o);
            if (t2 > m) m = t2;
        }
        if (r < 4) {
            int d = 63 - (int)(unsigned)(m & 0xffffffffULL);
            selD[r] = d;
            float srcv = (d < 32) ? v0 : v1;
            selV[r] = __shfl_sync(0xffffffffu, srcv, d & 31);
            if (d < 32) { if (lane == d) { k0 = 0; s0 = true; } }
            else        { if (lane == (d - 32)) { k1 = 0; s1 = true; } }
            if (r == 3) abs4 = __uint_as_float((unsigned)(m >> 32));
        } else {
            abs5 = __uint_as_float((unsigned)(m >> 32));
        }
    }

    int b = row >> 10, t = row & (T_ - 1);
    int bh = b * NH + h;

    if (tensor == 0) {
        if (lane == 0) {
#pragma unroll
            for (int a = 0; a < 3; ++a)
#pragma unroll
                for (int c = 0; c < 3; ++c)
                    if (selD[c + 1] < selD[c]) {
                        int td = selD[c]; selD[c] = selD[c + 1]; selD[c + 1] = td;
                        float tv = selV[c]; selV[c] = selV[c + 1]; selV[c + 1] = tv;
                    }
            size_t base = ((size_t)bh * T_ + t) * 4;
#pragma unroll
            for (int r = 0; r < 4; ++r) { g_Q4i[base + r] = selD[r]; g_Q4v[base + r] = selV[r]; }
        }
    } else if (tensor == 1) {
        g_KT[((size_t)bh * HD + lane) * T_ + t]      = s0 ? v0 : 0.f;
        g_KT[((size_t)bh * HD + 32 + lane) * T_ + t] = s1 ? v1 : 0.f;
    } else {
        g_V[((size_t)bh * T_ + t) * HD + lane]      = s0 ? v0 : 0.f;
        g_V[((size_t)bh * T_ + t) * HD + 32 + lane] = s1 ? v1 : 0.f;
        if (lane == 0 && (abs4 - abs5) < VGUARD) {
            int p = atomicAdd(&g_FixCount, 1);
            if (p < 4096) g_FixList[p] = (bh << 10) | t;
        }
    }
}

// ---------------- vfix: exact fp32 recompute + reselect (k split 4-way over 256 threads) ----------------
__global__ void __launch_bounds__(256) vfix_kernel(const float* __restrict__ x,
                                                   const float* __restrict__ wv) {
    __shared__ float part[4][64];
    __shared__ float vals[64];
    __shared__ int   selm[64];
    int cnt = g_FixCount; if (cnt > 4096) cnt = 4096;
    int f = threadIdx.x & 63, s = threadIdx.x >> 6;
    for (int i = blockIdx.x; i < cnt; i += gridDim.x) {
        int unit = g_FixList[i];
        int bh = unit >> 10, t = unit & (T_ - 1);
        int b = bh >> 4, h = bh & 15;
        int row = b * T_ + t;
        const float4* xr = (const float4*)(x + (size_t)row * DM) + s * 64;
        const float4* wr = (const float4*)(wv + (size_t)(h * HD + f) * DM) + s * 64;
        float acc = 0.f;
#pragma unroll 4
        for (int k = 0; k < 64; ++k) {
            float4 a = xr[k], w = wr[k];
            acc += a.x * w.x; acc += a.y * w.y; acc += a.z * w.z; acc += a.w * w.w;
        }
        part[s][f] = acc;
        __syncthreads();
        if (threadIdx.x < 64)
            vals[threadIdx.x] = part[0][threadIdx.x] + part[1][threadIdx.x]
                              + part[2][threadIdx.x] + part[3][threadIdx.x];
        __syncthreads();
        if (threadIdx.x < 32) {
            int lane = threadIdx.x;
            float v0 = vals[lane], v1 = vals[lane + 32];
            unsigned a0 = __float_as_uint(v0) & 0x7fffffffu;
            unsigned a1 = __float_as_uint(v1) & 0x7fffffffu;
            unsigned long long k0 = ((unsigned long long)a0 << 32) | (unsigned)(63 - lane);
            unsigned long long k1 = ((unsigned long long)a1 << 32) | (unsigned)(31 - lane);
            bool s0 = false, s1 = false;
#pragma unroll
            for (int r = 0; r < 4; ++r) {
                unsigned long long m = (k0 > k1) ? k0 : k1;
#pragma unroll
                for (int o = 16; o; o >>= 1) {
                    unsigned long long t2 = __shfl_xor_sync(0xffffffffu, m, o);
                    if (t2 > m) m = t2;
                }
                int d = 63 - (int)(unsigned)(m & 0xffffffffULL);
                if (d < 32) { if (lane == d) { k0 = 0; s0 = true; } }
                else        { if (lane == (d - 32)) { k1 = 0; s1 = true; } }
            }
            selm[lane] = s0 ? 1 : 0;
            selm[lane + 32] = s1 ? 1 : 0;
        }
        __syncthreads();
        if (threadIdx.x < 64)
            g_V[((size_t)bh * T_ + t) * HD + threadIdx.x] = selm[threadIdx.x] ? vals[threadIdx.x] : 0.f;
        __syncthreads();
    }
}

// ---------------- attention: proven block-radix top-64 (round-9 version) ----------------
__global__ void __launch_bounds__(256) attn_kernel() {
    int t  = blockIdx.x;
    int bh = blockIdx.y;
    int tid = threadIdx.x;
    int lane = tid & 31, wid = tid >> 5;

    __shared__ float    sc[T_];
    __shared__ unsigned su[T_];
    __shared__ int      hist[256];
    __shared__ int      candA[T_], candB[T_];
    __shared__ int      s_bin, s_remsh, s_C, s_cnt;
    __shared__ float    s_red[2];
    __shared__ int      selid[64];
    __shared__ float    selsc[64], selw[64];
    __shared__ int      wsum[8];
    __shared__ int      cls_sum[8];
    __shared__ float    part[256];
    __shared__ int      qidx[4];
    __shared__ float    qval[4];

    if (tid == 0) s_cnt = 0;
    if (tid < 4) {
        size_t qb = ((size_t)bh * T_ + t) * 4 + tid;
        qidx[tid] = g_Q4i[qb];
        qval[tid] = g_Q4v[qb];
    }
    __syncthreads();

    const float NEG = __int_as_float(0xff800000);
    const float* K0 = g_KT + ((size_t)bh * HD + qidx[0]) * T_;
    const float* K1 = g_KT + ((size_t)bh * HD + qidx[1]) * T_;
    const float* K2 = g_KT + ((size_t)bh * HD + qidx[2]) * T_;
    const float* K3 = g_KT + ((size_t)bh * HD + qidx[3]) * T_;
    float q0 = qval[0], q1 = qval[1], q2 = qval[2], q3 = qval[3];

    int n = t + 1;
#pragma unroll
    for (int r = 0; r < 4; ++r) {
        int i = tid + r * 256;
        unsigned u = 0u;
        if (i < n) {
            float s = (q0 * K0[i] + q1 * K1[i] + q2 * K2[i] + q3 * K3[i]) * 0.125f;
            sc[i] = s;
            unsigned bits = __float_as_uint(s);
            if (bits == 0x80000000u) bits = 0u;
            u = (bits & 0x80000000u) ? ~bits : (bits | 0x80000000u);
        }
        su[i] = u;
    }
    __syncthreads();

    int base = tid * 4;
    unsigned u4[4];
    int pl = 0, zl = 0;
#pragma unroll
    for (int c = 0; c < 4; ++c) {
        u4[c] = su[base + c];
        pl += (u4[c] > 0x80000000u);
        zl += (u4[c] == 0x80000000u);
    }
    int packedc = pl | (zl << 16);
#pragma unroll
    for (int o = 16; o; o >>= 1) packedc += __shfl_xor_sync(0xffffffffu, packedc, o);
    if (lane == 0) cls_sum[wid] = packedc;
    __syncthreads();
    int tot = 0;
#pragma unroll
    for (int w = 0; w < 8; ++w) tot += cls_sum[w];
    int P = tot & 0xffff, Z = tot >> 16;

    unsigned thr = 0u; int need_eq = 0;
    if (n <= 64) {
        thr = 0u; need_eq = 0;
    } else if (P < 64 && P + Z >= 64) {
        thr = 0x80000000u; need_eq = 64 - P;
    } else {
        bool wantPos = (P >= 64);
        if (tid == 0) s_C = 0;
        __syncthreads();
#pragma unroll
        for (int c = 0; c < 4; ++c) {
            int i = base + c;
            bool take = wantPos ? (u4[c] > 0x80000000u) : (i < n);
            unsigned m = __ballot_sync(0xffffffffu, take);
            int cw = __popc(m);
            int pos = __popc(m & ((1u << lane) - 1u));
            int wb = 0;
            if (lane == 0 && cw) wb = atomicAdd(&s_C, cw);
            wb = __shfl_sync(0xffffffffu, wb, 0);
            if (take) candA[wb + pos] = i;
        }
        __syncthreads();
        int C = s_C;
        __syncthreads();
        int rem = 64;
        unsigned pref = 0u;
        int* cur = candA; int* nxt = candB;
        bool fullkey = true;
        for (int shift = 24; shift >= 0; shift -= 8) {
            if (C == 1) { fullkey = false; break; }
            hist[tid] = 0;
            if (tid == 0) s_C = 0;
            __syncthreads();
            int rounds = (C + 255) >> 8;
            for (int r = 0; r < rounds; ++r) {
                int j = r * 256 + tid;
                int b = (j < C) ? (int)((su[cur[j]] >> shift) & 255u) : -1;
                unsigned m = __match_any_sync(0xffffffffu, b);
                if (b >= 0 && (int)__ffs(m) - 1 == lane) atomicAdd(&hist[b], __popc(m));
            }
            __syncthreads();
            if (wid == 0) {
                int bs = lane * 8;
                int loc[8]; int ssum = 0;
#pragma unroll
                for (int k = 7; k >= 0; --k) { ssum += hist[bs + k]; loc[k] = ssum; }
                int g = ssum;
#pragma unroll
                for (int off = 1; off < 32; off <<= 1) {
                    int v = __shfl_down_sync(0xffffffffu, g, off);
                    if (lane + off < 32) g += v;
                }
                int Hh = g - ssum;
#pragma unroll
                for (int k = 7; k >= 0; --k) {
                    int suf = loc[k] + Hh;
                    int nx2 = (k == 7) ? Hh : (loc[k + 1] + Hh);
                    if (suf >= rem && nx2 < rem) { s_bin = bs + k; s_remsh = rem - nx2; }
                }
            }
            __syncthreads();
            int b2 = s_bin; rem = s_remsh;
            int rounds2 = (C + 255) >> 8;
            for (int r = 0; r < rounds2; ++r) {
                int j = r * 256 + tid;
                if (j < C && (int)((su[cur[j]] >> shift) & 255u) == b2) {
                    int p = atomicAdd(&s_C, 1); nxt[p] = cur[j];
                }
            }
            __syncthreads();
            C = s_C;
            __syncthreads();
            pref |= (unsigned)b2 << shift;
            int* tsw = cur; cur = nxt; nxt = tsw;
        }
        thr = fullkey ? pref : su[cur[0]];
        need_eq = rem;
    }

    int eqf[4]; int local = 0;
#pragma unroll
    for (int c = 0; c < 4; ++c) { eqf[c] = (u4[c] == thr) ? 1 : 0; local += eqf[c]; }
    int v = local;
#pragma unroll
    for (int o = 1; o < 32; o <<= 1) {
        int x = __shfl_up_sync(0xffffffffu, v, o);
        if (lane >= o) v += x;
    }
    if (lane == 31) wsum[wid] = v;
    __syncthreads();
    if (tid == 0) { int a = 0; for (int w = 0; w < 8; ++w) { int x = wsum[w]; wsum[w] = a; a += x; } }
    __syncthreads();
    int run = v - local + wsum[wid];

#pragma unroll
    for (int c = 0; c < 4; ++c) {
        int i = base + c; unsigned u = u4[c];
        bool sel = false;
        if (u > thr) sel = true;
        else if (eqf[c]) { sel = (run < need_eq); run++; }
        if (sel) {
            int p = atomicAdd(&s_cnt, 1);
            if (p < 64) { selid[p] = i; selsc[p] = sc[i]; }
        }
    }
    __syncthreads();
    int cnt = s_cnt; if (cnt > 64) cnt = 64;

    if (tid < 64) {
        float xx = (tid < cnt) ? selsc[tid] : NEG;
#pragma unroll
        for (int o = 16; o; o >>= 1) xx = fmaxf(xx, __shfl_xor_sync(0xffffffffu, xx, o));
        if ((tid & 31) == 0) s_red[tid >> 5] = xx;
    }
    __syncthreads();
    float m = fmaxf(s_red[0], s_red[1]);
    __syncthreads();
    if (tid < 64) {
        float e = (tid < cnt) ? __expf(selsc[tid] - m) : 0.f;
        selw[tid] = e;
#pragma unroll
        for (int o = 16; o; o >>= 1) e += __shfl_xor_sync(0xffffffffu, e, o);
        if ((tid & 31) == 0) s_red[tid >> 5] = e;
    }
    __syncthreads();
    float invZ = 1.f / (s_red[0] + s_red[1]);

    int g = tid >> 6, d = tid & 63;
    float acc = 0.f;
    const float* Vb = g_V + (size_t)bh * T_ * HD;
    for (int p = g; p < cnt; p += 4) acc += selw[p] * Vb[(size_t)selid[p] * HD + d];
    part[tid] = acc;
    __syncthreads();
    if (tid < 64) {
        float o = (part[tid] + part[tid + 64] + part[tid + 128] + part[tid + 192]) * invZ;
        int b = bh >> 4, h = bh & 15;
        g_AO[((size_t)(b * T_ + t)) * DM + h * HD + tid] = o;
    }
}

// ---------------- launch ----------------
extern "C" void kernel_launch(void* const* d_in, const int* in_sizes, int n_in,
                              void* d_out, int out_size) {
    const float* x  = (const float*)d_in[0];
    const float* wq = (const float*)d_in[1];
    const float* wk = (const float*)d_in[2];
    const float* wv = (const float*)d_in[3];
    const float* wo = (const float*)d_in[4];
    float* out = (float*)d_out;

    sgemm_qk<<<dim3(DM / BN, ROWS / BM, 2), 256>>>(x, wq, wk);

    mma_gemm_v<<<dim3(DM / 128, ROWS / 128), 256>>>(x, wv);

    sparsify_kernel<<<(3 * UNITS) / 8, 256>>>();

    vfix_kernel<<<512, 256>>>(x, wv);

    attn_kernel<<<dim3(T_, B_ * NH), 256>>>();

    mma_gemm_o<<<dim3(DM / 128, ROWS / 128), 256>>>(wo, out);
}

// round 16
// speedup vs baseline: 1.4234x; 1.2293x over previous
#include <cuda_runtime.h>
#include <cstdint>

#define B_    4
#define T_    1024
#define DM    1024
#define NH    16
#define HD    64
#define ROWS  (B_ * T_)        // 4096
#define UNITS (ROWS * NH)      // 65536
#define VGUARD 1e-4f
#define CANDMAX 384

// ---------------- static device scratch (no allocations allowed) ----------------
__device__ float g_Y[3][ROWS * DM];       // raw Q/K/V projections   48 MB
__device__ float g_KT[64 * HD * T_];      // sparsified K, [bh][d][t] 16 MB
__device__ float g_V[UNITS * HD];         // sparsified V 16 MB
__device__ float g_Q4v[UNITS * 4];        // top-4 q values
__device__ int   g_Q4i[UNITS * 4];        // top-4 q indices (ascending)
__device__ float g_AO[ROWS * DM];         // attention output 16 MB
__device__ int   g_FixCount;              // V-units needing exact recompute
__device__ int   g_FixList[4096];

// =================== fp32 FFMA SGEMM (Q,K) — at FFMA roofline, unchanged ===================
#define BM  128
#define BN  128
#define BKK 16
#define BMP (BM + 4)

__device__ __forceinline__ void sgemm_db_body(const float* __restrict__ X,
                                              const float* __restrict__ W,
                                              float* __restrict__ Y) {
    __shared__ float As[2][BKK][BMP];
    __shared__ float Bs[2][BKK][BMP];
    int tid = threadIdx.x;
    int tx = tid & 15, ty = tid >> 4;
    int m0 = blockIdx.y * BM, n0 = blockIdx.x * BN;

    float acc[8][8];
#pragma unroll
    for (int i = 0; i < 8; ++i)
#pragma unroll
        for (int j = 0; j < 8; ++j) acc[i][j] = 0.f;

    int lr = tid >> 2;
    int lc = tid & 3;

#pragma unroll
    for (int rr = 0; rr < 2; ++rr) {
        int r = lr + rr * 64;
        float4 a = *(const float4*)(X + (size_t)(m0 + r) * DM + lc * 4);
        As[0][lc * 4 + 0][r] = a.x; As[0][lc * 4 + 1][r] = a.y;
        As[0][lc * 4 + 2][r] = a.z; As[0][lc * 4 + 3][r] = a.w;
        float4 b = *(const float4*)(W + (size_t)(n0 + r) * DM + lc * 4);
        Bs[0][lc * 4 + 0][r] = b.x; Bs[0][lc * 4 + 1][r] = b.y;
        Bs[0][lc * 4 + 2][r] = b.z; Bs[0][lc * 4 + 3][r] = b.w;
    }
    __syncthreads();

    for (int c = 0; c < DM / BKK; ++c) {
        int cur = c & 1, nxt = cur ^ 1;
        bool hn = (c + 1) < DM / BKK;
        float4 pa0, pa1, pb0, pb1;
        if (hn) {
            int kn = (c + 1) * BKK;
            pa0 = *(const float4*)(X + (size_t)(m0 + lr) * DM + kn + lc * 4);
            pa1 = *(const float4*)(X + (size_t)(m0 + lr + 64) * DM + kn + lc * 4);
            pb0 = *(const float4*)(W + (size_t)(n0 + lr) * DM + kn + lc * 4);
            pb1 = *(const float4*)(W + (size_t)(n0 + lr + 64) * DM + kn + lc * 4);
        }
#pragma unroll
        for (int kk = 0; kk < BKK; ++kk) {
            float4 a0 = *(const float4*)&As[cur][kk][ty * 4];
            float4 a1 = *(const float4*)&As[cur][kk][64 + ty * 4];
            float4 b0 = *(const float4*)&Bs[cur][kk][tx * 4];
            float4 b1 = *(const float4*)&Bs[cur][kk][64 + tx * 4];
            float a[8] = {a0.x, a0.y, a0.z, a0.w, a1.x, a1.y, a1.z, a1.w};
            float b[8] = {b0.x, b0.y, b0.z, b0.w, b1.x, b1.y, b1.z, b1.w};
#pragma unroll
            for (int i = 0; i < 8; ++i)
#pragma unroll
                for (int j = 0; j < 8; ++j) acc[i][j] = fmaf(a[i], b[j], acc[i][j]);
        }
        if (hn) {
            As[nxt][lc * 4 + 0][lr] = pa0.x; As[nxt][lc * 4 + 1][lr] = pa0.y;
            As[nxt][lc * 4 + 2][lr] = pa0.z; As[nxt][lc * 4 + 3][lr] = pa0.w;
            As[nxt][lc * 4 + 0][lr + 64] = pa1.x; As[nxt][lc * 4 + 1][lr + 64] = pa1.y;
            As[nxt][lc * 4 + 2][lr + 64] = pa1.z; As[nxt][lc * 4 + 3][lr + 64] = pa1.w;
            Bs[nxt][lc * 4 + 0][lr] = pb0.x; Bs[nxt][lc * 4 + 1][lr] = pb0.y;
            Bs[nxt][lc * 4 + 2][lr] = pb0.z; Bs[nxt][lc * 4 + 3][lr] = pb0.w;
            Bs[nxt][lc * 4 + 0][lr + 64] = pb1.x; Bs[nxt][lc * 4 + 1][lr + 64] = pb1.y;
            Bs[nxt][lc * 4 + 2][lr + 64] = pb1.z; Bs[nxt][lc * 4 + 3][lr + 64] = pb1.w;
        }
        __syncthreads();
    }
#pragma unroll
    for (int i = 0; i < 8; ++i) {
        int r = m0 + ((i < 4) ? (ty * 4 + i) : (64 + ty * 4 + (i - 4)));
        float* yp = Y + (size_t)r * DM + n0;
        *(float4*)(yp + tx * 4) = make_float4(acc[i][0], acc[i][1], acc[i][2], acc[i][3]);
        *(float4*)(yp + 64 + tx * 4) = make_float4(acc[i][4], acc[i][5], acc[i][6], acc[i][7]);
    }
}

__global__ void __launch_bounds__(256) sgemm_qk(const float* __restrict__ X,
                                                const float* __restrict__ Wq,
                                                const float* __restrict__ Wk) {
    const float* W = (blockIdx.z == 0) ? Wq : Wk;
    sgemm_db_body(X, W, g_Y[blockIdx.z]);
}

// =================== bf16x3 warp-MMA GEMM (V projection + O projection) ===================
#define LDW   12

__device__ __forceinline__ unsigned cvt2(float hi, float lo) {
    unsigned r;
    asm("cvt.rn.bf16x2.f32 %0, %1, %2;" : "=r"(r) : "f"(hi), "f"(lo));
    return r;
}
__device__ __forceinline__ void mma_bf16(float* c, const unsigned* a, const unsigned* b) {
    asm volatile(
        "mma.sync.aligned.m16n8k16.row.col.f32.bf16.bf16.f32 "
        "{%0,%1,%2,%3}, {%4,%5,%6,%7}, {%8,%9}, {%0,%1,%2,%3};"
        : "+f"(c[0]), "+f"(c[1]), "+f"(c[2]), "+f"(c[3])
        : "r"(a[0]), "r"(a[1]), "r"(a[2]), "r"(a[3]), "r"(b[0]), "r"(b[1]));
}

__device__ __forceinline__ void split_store3(unsigned* S0, unsigned* S1, unsigned* S2,
                                             int r, int c4, float4 a) {
    unsigned p0 = cvt2(a.y, a.x);
    float h0 = __uint_as_float(p0 & 0xffff0000u), l0 = __uint_as_float(p0 << 16);
    float rx = a.x - l0, ry = a.y - h0;
    unsigned p1 = cvt2(ry, rx);
    float h1 = __uint_as_float(p1 & 0xffff0000u), l1 = __uint_as_float(p1 << 16);
    unsigned p2 = cvt2(ry - h1, rx - l1);
    unsigned q0 = cvt2(a.w, a.z);
    float h2 = __uint_as_float(q0 & 0xffff0000u), l2 = __uint_as_float(q0 << 16);
    float rz = a.z - l2, rw = a.w - h2;
    unsigned q1 = cvt2(rw, rz);
    float h3 = __uint_as_float(q1 & 0xffff0000u), l3 = __uint_as_float(q1 << 16);
    unsigned q2 = cvt2(rw - h3, rz - l3);
    int o = r * LDW + c4 * 2;
    *(uint2*)&S0[o] = make_uint2(p0, q0);
    *(uint2*)&S1[o] = make_uint2(p1, q1);
    *(uint2*)&S2[o] = make_uint2(p2, q2);
}

__device__ __forceinline__ void mma3_body(const float* __restrict__ X,
                                          const float* __restrict__ W,
                                          float* __restrict__ Y) {
    __shared__ unsigned A0s[128 * LDW], A1s[128 * LDW], A2s[128 * LDW];
    __shared__ unsigned B0s[128 * LDW], B1s[128 * LDW], B2s[128 * LDW];
    int tid = threadIdx.x, lane = tid & 31, wid = tid >> 5;
    int m0 = blockIdx.y * 128, n0 = blockIdx.x * 128;
    int wm = (wid >> 2) * 64, wn = (wid & 3) * 32;
    int gid = lane >> 2, tig = lane & 3;

    float acc[4][4][4];
#pragma unroll
    for (int i = 0; i < 4; ++i)
#pragma unroll
        for (int j = 0; j < 4; ++j)
#pragma unroll
            for (int q = 0; q < 4; ++q) acc[i][j][q] = 0.f;

    int lr = tid >> 2, lc4 = tid & 3;

#pragma unroll
    for (int i = 0; i < 2; ++i) {
        int r = lr + i * 64;
        split_store3(A0s, A1s, A2s, r, lc4, *(const float4*)(X + (size_t)(m0 + r) * DM + lc4 * 4));
        split_store3(B0s, B1s, B2s, r, lc4, *(const float4*)(W + (size_t)(n0 + r) * DM + lc4 * 4));
    }
    __syncthreads();

    for (int c = 0; c < DM / 16; ++c) {
        float4 pa[2], pb[2];
        bool has_next = (c + 1) < DM / 16;
        if (has_next) {
            int kn = (c + 1) * 16;
#pragma unroll
            for (int i = 0; i < 2; ++i) {
                int r = lr + i * 64;
                pa[i] = *(const float4*)(X + (size_t)(m0 + r) * DM + kn + lc4 * 4);
                pb[i] = *(const float4*)(W + (size_t)(n0 + r) * DM + kn + lc4 * 4);
            }
        }
        {
            unsigned b0[4][2], b1[4][2], b2[4][2];
#pragma unroll
            for (int j = 0; j < 4; ++j) {
                int nn = (wn + j * 8 + gid) * LDW;
                b0[j][0] = B0s[nn + tig]; b0[j][1] = B0s[nn + tig + 4];
                b1[j][0] = B1s[nn + tig]; b1[j][1] = B1s[nn + tig + 4];
                b2[j][0] = B2s[nn + tig]; b2[j][1] = B2s[nn + tig + 4];
            }
            unsigned af[4][4];
#pragma unroll
            for (int i = 0; i < 4; ++i) {
                int r0 = (wm + i * 16 + gid) * LDW, r1 = r0 + 8 * LDW;
                af[i][0] = A0s[r0 + tig]; af[i][1] = A0s[r1 + tig];
                af[i][2] = A0s[r0 + tig + 4]; af[i][3] = A0s[r1 + tig + 4];
            }
#pragma unroll
            for (int i = 0; i < 4; ++i)
#pragma unroll
                for (int j = 0; j < 4; ++j) {
                    mma_bf16(acc[i][j], af[i], b0[j]);
                    mma_bf16(acc[i][j], af[i], b1[j]);
                    mma_bf16(acc[i][j], af[i], b2[j]);
                }
#pragma unroll
            for (int i = 0; i < 4; ++i) {
                int r0 = (wm + i * 16 + gid) * LDW, r1 = r0 + 8 * LDW;
                af[i][0] = A1s[r0 + tig]; af[i][1] = A1s[r1 + tig];
                af[i][2] = A1s[r0 + tig + 4]; af[i][3] = A1s[r1 + tig + 4];
            }
#pragma unroll
            for (int i = 0; i < 4; ++i)
#pragma unroll
                for (int j = 0; j < 4; ++j) {
                    mma_bf16(acc[i][j], af[i], b0[j]);
                    mma_bf16(acc[i][j], af[i], b1[j]);
                }
#pragma unroll
            for (int i = 0; i < 4; ++i) {
                int r0 = (wm + i * 16 + gid) * LDW, r1 = r0 + 8 * LDW;
                af[i][0] = A2s[r0 + tig]; af[i][1] = A2s[r1 + tig];
                af[i][2] = A2s[r0 + tig + 4]; af[i][3] = A2s[r1 + tig + 4];
            }
#pragma unroll
            for (int i = 0; i < 4; ++i)
#pragma unroll
                for (int j = 0; j < 4; ++j)
                    mma_bf16(acc[i][j], af[i], b0[j]);
        }
        __syncthreads();
        if (has_next) {
#pragma unroll
            for (int i = 0; i < 2; ++i) {
                int r = lr + i * 64;
                split_store3(A0s, A1s, A2s, r, lc4, pa[i]);
                split_store3(B0s, B1s, B2s, r, lc4, pb[i]);
            }
            __syncthreads();
        }
    }

#pragma unroll
    for (int i = 0; i < 4; ++i) {
        int r0 = m0 + wm + i * 16 + gid, r1 = r0 + 8;
#pragma unroll
        for (int j = 0; j < 4; ++j) {
            int cb = n0 + wn + j * 8 + 2 * tig;
            *(float2*)(Y + (size_t)r0 * DM + cb) = make_float2(acc[i][j][0], acc[i][j][1]);
            *(float2*)(Y + (size_t)r1 * DM + cb) = make_float2(acc[i][j][2], acc[i][j][3]);
        }
    }
}

__global__ void __launch_bounds__(256, 2) mma_gemm_v(const float* __restrict__ X,
                                                     const float* __restrict__ Wv) {
    if (blockIdx.x == 0 && blockIdx.y == 0 && threadIdx.x == 0) g_FixCount = 0;
    mma3_body(X, Wv, g_Y[2]);
}
__global__ void __launch_bounds__(256, 2) mma_gemm_o(const float* __restrict__ Wo,
                                                     float* __restrict__ Y) {
    mma3_body(g_AO, Wo, Y);
}

// ---------------- sparsify (unchanged, with V guard) ----------------
__global__ void __launch_bounds__(256) sparsify_kernel() {
    int warp = (blockIdx.x * blockDim.x + threadIdx.x) >> 5;
    int lane = threadIdx.x & 31;
    int tensor = warp / UNITS;
    int idx = warp - tensor * UNITS;
    int row = idx >> 4;
    int h = idx & 15;

    const float* Y = g_Y[tensor];
    float v0 = Y[(size_t)row * DM + h * HD + lane];
    float v1 = Y[(size_t)row * DM + h * HD + 32 + lane];
    unsigned a0 = __float_as_uint(v0) & 0x7fffffffu;
    unsigned a1 = __float_as_uint(v1) & 0x7fffffffu;
    unsigned long long k0 = ((unsigned long long)a0 << 32) | (unsigned)(63 - lane);
    unsigned long long k1 = ((unsigned long long)a1 << 32) | (unsigned)(31 - lane);

    bool s0 = false, s1 = false;
    int selD[4]; float selV[4];
    float abs4 = 0.f, abs5 = 0.f;
    int rounds = (tensor == 2) ? 5 : 4;
    for (int r = 0; r < rounds; ++r) {
        unsigned long long m = (k0 > k1) ? k0 : k1;
#pragma unroll
        for (int o = 16; o; o >>= 1) {
            unsigned long long t2 = __shfl_xor_sync(0xffffffffu, m, o);
            if (t2 > m) m = t2;
        }
        if (r < 4) {
            int d = 63 - (int)(unsigned)(m & 0xffffffffULL);
            selD[r] = d;
            float srcv = (d < 32) ? v0 : v1;
            selV[r] = __shfl_sync(0xffffffffu, srcv, d & 31);
            if (d < 32) { if (lane == d) { k0 = 0; s0 = true; } }
            else        { if (lane == (d - 32)) { k1 = 0; s1 = true; } }
            if (r == 3) abs4 = __uint_as_float((unsigned)(m >> 32));
        } else {
            abs5 = __uint_as_float((unsigned)(m >> 32));
        }
    }

    int b = row >> 10, t = row & (T_ - 1);
    int bh = b * NH + h;

    if (tensor == 0) {
        if (lane == 0) {
#pragma unroll
            for (int a = 0; a < 3; ++a)
#pragma unroll
                for (int c = 0; c < 3; ++c)
                    if (selD[c + 1] < selD[c]) {
                        int td = selD[c]; selD[c] = selD[c + 1]; selD[c + 1] = td;
                        float tv = selV[c]; selV[c] = selV[c + 1]; selV[c + 1] = tv;
                    }
            size_t base = ((size_t)bh * T_ + t) * 4;
#pragma unroll
            for (int r = 0; r < 4; ++r) { g_Q4i[base + r] = selD[r]; g_Q4v[base + r] = selV[r]; }
        }
    } else if (tensor == 1) {
        g_KT[((size_t)bh * HD + lane) * T_ + t]      = s0 ? v0 : 0.f;
        g_KT[((size_t)bh * HD + 32 + lane) * T_ + t] = s1 ? v1 : 0.f;
    } else {
        g_V[((size_t)bh * T_ + t) * HD + lane]      = s0 ? v0 : 0.f;
        g_V[((size_t)bh * T_ + t) * HD + 32 + lane] = s1 ? v1 : 0.f;
        if (lane == 0 && (abs4 - abs5) < VGUARD) {
            int p = atomicAdd(&g_FixCount, 1);
            if (p < 4096) g_FixList[p] = (bh << 10) | t;
        }
    }
}

// ---------------- vfix (unchanged round-14 version) ----------------
__global__ void __launch_bounds__(256) vfix_kernel(const float* __restrict__ x,
                                                   const float* __restrict__ wv) {
    __shared__ float part[4][64];
    __shared__ float vals[64];
    __shared__ int   selm[64];
    int cnt = g_FixCount; if (cnt > 4096) cnt = 4096;
    int f = threadIdx.x & 63, s = threadIdx.x >> 6;
    for (int i = blockIdx.x; i < cnt; i += gridDim.x) {
        int unit = g_FixList[i];
        int bh = unit >> 10, t = unit & (T_ - 1);
        int b = bh >> 4, h = bh & 15;
        int row = b * T_ + t;
        const float4* xr = (const float4*)(x + (size_t)row * DM) + s * 64;
        const float4* wr = (const float4*)(wv + (size_t)(h * HD + f) * DM) + s * 64;
        float acc = 0.f;
#pragma unroll 4
        for (int k = 0; k < 64; ++k) {
            float4 a = xr[k], w = wr[k];
            acc += a.x * w.x; acc += a.y * w.y; acc += a.z * w.z; acc += a.w * w.w;
        }
        part[s][f] = acc;
        __syncthreads();
        if (threadIdx.x < 64)
            vals[threadIdx.x] = part[0][threadIdx.x] + part[1][threadIdx.x]
                              + part[2][threadIdx.x] + part[3][threadIdx.x];
        __syncthreads();
        if (threadIdx.x < 32) {
            int lane = threadIdx.x;
            float v0 = vals[lane], v1 = vals[lane + 32];
            unsigned a0 = __float_as_uint(v0) & 0x7fffffffu;
            unsigned a1 = __float_as_uint(v1) & 0x7fffffffu;
            unsigned long long k0 = ((unsigned long long)a0 << 32) | (unsigned)(63 - lane);
            unsigned long long k1 = ((unsigned long long)a1 << 32) | (unsigned)(31 - lane);
            bool s0 = false, s1 = false;
#pragma unroll
            for (int r = 0; r < 4; ++r) {
                unsigned long long m = (k0 > k1) ? k0 : k1;
#pragma unroll
                for (int o = 16; o; o >>= 1) {
                    unsigned long long t2 = __shfl_xor_sync(0xffffffffu, m, o);
                    if (t2 > m) m = t2;
                }
                int d = 63 - (int)(unsigned)(m & 0xffffffffULL);
                if (d < 32) { if (lane == d) { k0 = 0; s0 = true; } }
                else        { if (lane == (d - 32)) { k1 = 0; s1 = true; } }
            }
            selm[lane] = s0 ? 1 : 0;
            selm[lane + 32] = s1 ? 1 : 0;
        }
        __syncthreads();
        if (threadIdx.x < 64)
            g_V[((size_t)bh * T_ + t) * HD + threadIdx.x] = selm[threadIdx.x] ? vals[threadIdx.x] : 0.f;
        __syncthreads();
    }
}

// ---------------- attention: WARP-PER-ROW, no block barriers ----------------
// Semantics identical to the proven block version:
//   keys: monotone map, -0 canonicalized; invalid positions carry key 0.
//   n<=64: all valid. P<64<=P+Z: thr=key(0), need=64-P.
//   else: thr = 64th-largest candidate key (positives if P>=64, else all valid),
//         need = 64 - count(>thr); tie-break by lowest index (chunk-ordered ballots).
__device__ __forceinline__ unsigned key_of(float s) {
    unsigned b = __float_as_uint(s);
    if (b == 0x80000000u) b = 0u;
    return (b & 0x80000000u) ? ~b : (b | 0x80000000u);
}

__global__ void __launch_bounds__(256) attn_kernel() {
    __shared__ float    swsc[8][T_];          // 32 KB scores
    __shared__ unsigned swcand[8][CANDMAX];   // 12 KB candidate keys
    __shared__ int      swsel[8][64];         //  2 KB selected idx
    __shared__ float    swsw[8][64];          //  2 KB selected score/weight

    int lane = threadIdx.x & 31, wid = threadIdx.x >> 5;
    int row = blockIdx.x * 8 + wid;           // bh*1024 + t
    int t = row & (T_ - 1), bh = row >> 10;
    unsigned lmlt = (1u << lane) - 1u;
    const unsigned FULL = 0xffffffffu;

    // q top-4
    float qv = 0.f; int qi = 0;
    if (lane < 4) {
        size_t qb = ((size_t)bh * T_ + t) * 4 + lane;
        qi = g_Q4i[qb]; qv = g_Q4v[qb];
    }
    int i0 = __shfl_sync(FULL, qi, 0), i1 = __shfl_sync(FULL, qi, 1);
    int i2 = __shfl_sync(FULL, qi, 2), i3 = __shfl_sync(FULL, qi, 3);
    float q0 = __shfl_sync(FULL, qv, 0), q1 = __shfl_sync(FULL, qv, 1);
    float q2 = __shfl_sync(FULL, qv, 2), q3 = __shfl_sync(FULL, qv, 3);
    const float* K0 = g_KT + ((size_t)bh * HD + i0) * T_;
    const float* K1 = g_KT + ((size_t)bh * HD + i1) * T_;
    const float* K2 = g_KT + ((size_t)bh * HD + i2) * T_;
    const float* K3 = g_KT + ((size_t)bh * HD + i3) * T_;

    int n = t + 1;
    int chunks = (n + 31) >> 5;
    float* sc = swsc[wid];

    // scores + classification
    int pl = 0, zl = 0;
    for (int r = 0; r < chunks; ++r) {
        int i = r * 32 + lane;
        float s;
        if (i < n) s = (q0 * K0[i] + q1 * K1[i] + q2 * K2[i] + q3 * K3[i]) * 0.125f;
        else       s = __uint_as_float(0xFFFFFFFFu);   // sentinel: key_of == 0
        sc[i] = s;
        unsigned u = key_of(s);
        pl += (u > 0x80000000u);
        zl += (u == 0x80000000u);
    }
    int packed = pl | (zl << 16);
#pragma unroll
    for (int o = 16; o; o >>= 1) packed += __shfl_xor_sync(FULL, packed, o);
    int P = packed & 0xffff, Z = packed >> 16;

    unsigned thr = 0u; int need_eq = 0;
    if (n <= 64) {
        thr = 0u; need_eq = 0;
    } else if (P < 64 && P + Z >= 64) {
        thr = 0x80000000u; need_eq = 64 - P;
    } else {
        bool wantPos = (P >= 64);
        // compact candidate keys
        unsigned* cand = swcand[wid];
        int C = 0;
        for (int r = 0; r < chunks; ++r) {
            int i = r * 32 + lane;
            unsigned u = key_of(sc[i]);
            bool take = wantPos ? (u > 0x80000000u) : (i < n);
            unsigned mb = __ballot_sync(FULL, take);
            int pos = __popc(mb & lmlt);
            if (take && (C + pos) < CANDMAX) cand[C + pos] = u;
            C += __popc(mb);
        }
        unsigned v = 0u;
        int cgt = 0;
        if (C <= CANDMAX) {
            unsigned kr[12];
#pragma unroll
            for (int q = 0; q < 12; ++q) {
                int j = lane + q * 32;
                kr[q] = (j < C) ? cand[j] : 0u;
            }
            for (int bit = 31; bit >= 0; --bit) {
                unsigned test = v | (1u << bit);
                int c = 0;
#pragma unroll
                for (int q = 0; q < 12; ++q) c += (kr[q] >= test);
                c = (int)__reduce_add_sync(FULL, (unsigned)c);
                if (c >= 64) v = test;
            }
            int cg = 0;
#pragma unroll
            for (int q = 0; q < 12; ++q) cg += (kr[q] > v);
            cgt = (int)__reduce_add_sync(FULL, (unsigned)cg);
        } else {
            // ultra-rare robust path: bisect over smem scores
            for (int bit = 31; bit >= 0; --bit) {
                unsigned test = v | (1u << bit);
                int c = 0;
                for (int r = 0; r < chunks; ++r) {
                    int i = r * 32 + lane;
                    unsigned u = key_of(sc[i]);
                    bool candp = wantPos ? (u > 0x80000000u) : (i < n);
                    c += (candp && u >= test);
                }
                c = (int)__reduce_add_sync(FULL, (unsigned)c);
                if (c >= 64) v = test;
            }
            int cg = 0;
            for (int r = 0; r < chunks; ++r) {
                int i = r * 32 + lane;
                unsigned u = key_of(sc[i]);
                bool candp = wantPos ? (u > 0x80000000u) : (i < n);
                cg += (candp && u > v);
            }
            cgt = (int)__reduce_add_sync(FULL, (unsigned)cg);
        }
        thr = v; need_eq = 64 - cgt;
    }

    // final selection in index order (chunk-ordered ballots)
    int* sel = swsel[wid];
    float* sw = swsw[wid];
    int run_eq = 0, cnt = 0;
    for (int r = 0; r < chunks; ++r) {
        int i = r * 32 + lane;
        float s = sc[i];
        unsigned u = key_of(s);
        bool gt = (u > thr);
        bool eq = (u == thr);
        unsigned beq = __ballot_sync(FULL, eq);
        int eqr = run_eq + __popc(beq & lmlt);
        bool take = gt || (eq && eqr < need_eq);
        run_eq += __popc(beq);
        unsigned bs = __ballot_sync(FULL, take);
        int p = cnt + __popc(bs & lmlt);
        if (take && p < 64) { sel[p] = i; sw[p] = s; }
        cnt += __popc(bs);
    }
    if (cnt > 64) cnt = 64;

    // softmax over selected
    const float NEG = __int_as_float(0xff800000);
    float x0 = (lane < cnt) ? sw[lane] : NEG;
    float x1 = (lane + 32 < cnt) ? sw[lane + 32] : NEG;
    float mx = fmaxf(x0, x1);
#pragma unroll
    for (int o = 16; o; o >>= 1) mx = fmaxf(mx, __shfl_xor_sync(FULL, mx, o));
    float e0 = (lane < cnt) ? __expf(x0 - mx) : 0.f;
    float e1 = (lane + 32 < cnt) ? __expf(x1 - mx) : 0.f;
    float zs = e0 + e1;
#pragma unroll
    for (int o = 16; o; o >>= 1) zs += __shfl_xor_sync(FULL, zs, o);
    float invZ = 1.f / zs;
    __syncwarp();
    if (lane < cnt) sw[lane] = e0;
    if (lane + 32 < cnt) sw[lane + 32] = e1;
    __syncwarp();

    // attn * V: lane owns columns lane and lane+32
    const float* Vb = g_V + (size_t)bh * T_ * HD;
    float a0 = 0.f, a1 = 0.f;
    for (int p = 0; p < cnt; ++p) {
        float w = sw[p];
        const float* vr = Vb + (size_t)sel[p] * HD;
        a0 += w * vr[lane];
        a1 += w * vr[lane + 32];
    }
    int b = bh >> 4, h = bh & 15;
    float* op = g_AO + ((size_t)(b * T_ + t)) * DM + h * HD;
    op[lane] = a0 * invZ;
    op[lane + 32] = a1 * invZ;
}

// ---------------- launch ----------------
extern "C" void kernel_launch(void* const* d_in, const int* in_sizes, int n_in,
                              void* d_out, int out_size) {
    const float* x  = (const float*)d_in[0];
    const float* wq = (const float*)d_in[1];
    const float* wk = (const float*)d_in[2];
    const float* wv = (const float*)d_in[3];
    const float* wo = (const float*)d_in[4];
    float* out = (float*)d_out;

    sgemm_qk<<<dim3(DM / BN, ROWS / BM, 2), 256>>>(x, wq, wk);

    mma_gemm_v<<<dim3(DM / 128, ROWS / 128), 256>>>(x, wv);

    sparsify_kernel<<<(3 * UNITS) / 8, 256>>>();

    vfix_kernel<<<512, 256>>>(x, wv);

    attn_kernel<<<UNITS / 8, 256>>>();

    mma_gemm_o<<<dim3(DM / 128, ROWS / 128), 256>>>(wo, out);
}